// round 4
// baseline (speedup 1.0000x reference)
#include <cuda_runtime.h>

#define NITEMS 512
#define MAXM   256
#define DIM    128
#define ROWS_PER_ITEM 512
#define MAXPAIRS 131072

// Tree scratch: 512 items * 512 rows * 128 floats = 128 MB
__device__ float g_buf[(long)NITEMS * ROWS_PER_ITEM * DIM];
// Duplicated weights for f32x2 row-pair math: W*d[i][c] = (w, w)
__device__ float2 g_W1d[256 * 256];   // 512 KB
__device__ float2 g_W2d[256 * 128];   // 256 KB
// Batched pair lists
__device__ int g_src[MAXPAIRS];
__device__ int g_dst[MAXPAIRS];
__device__ int g_off[8 * NITEMS];
__device__ int g_count[8];
__device__ int g_base[8];

typedef unsigned long long ull;

__device__ __forceinline__ ull ffma2(ull a, ull b, ull c) {
    ull d; asm("fma.rn.f32x2 %0, %1, %2, %3;" : "=l"(d) : "l"(a), "l"(b), "l"(c));
    return d;
}
__device__ __forceinline__ ull bcast2(float x) {
    ull d; asm("mov.b64 %0, {%1, %1};" : "=l"(d) : "f"(x)); return d;
}
__device__ __forceinline__ ull pack2(float x, float y) {
    ull d; asm("mov.b64 %0, {%1, %2};" : "=l"(d) : "f"(x), "f"(y)); return d;
}
__device__ __forceinline__ float2 unpack2(ull v) {
    float2 r; asm("mov.b64 {%0, %1}, %2;" : "=f"(r.x), "=f"(r.y) : "l"(v)); return r;
}
__device__ __forceinline__ int get_limit(const int* lim, bool is64, int i) {
    return is64 ? lim[2 * i] : lim[i];
}

// ---------------------------------------------------------------------------
__global__ void k_wdup(const float* __restrict__ W1, const float* __restrict__ W2) {
    int i = blockIdx.x, c = threadIdx.x;
    float w = W1[i * 256 + c];
    g_W1d[i * 256 + c] = make_float2(w, w);
    if (c < 128) {
        float v = W2[i * 128 + c];
        g_W2d[i * 128 + c] = make_float2(v, v);
    }
}

// ---------------------------------------------------------------------------
__global__ void k_scatter(const float* __restrict__ args, const int* __restrict__ lim) {
    int item = blockIdx.y;
    bool is64 = (lim[1] == 0);
    int start = get_limit(lim, is64, item);
    int L     = get_limit(lim, is64, item + 1) - start;
    int row0  = blockIdx.x * 128;
    int nrows = min(128, L - row0);
    if (nrows <= 0) return;
    const float4* src = (const float4*)(args + (long)(start + row0) * DIM);
    float4* dst = (float4*)(g_buf + ((long)item * ROWS_PER_ITEM + row0) * DIM);
    int total = nrows * (DIM / 4);
    for (int f = threadIdx.x; f < total; f += blockDim.x) dst[f] = src[f];
}

// ---------------------------------------------------------------------------
// Scan: per-level totals + per-item exclusive offsets (no per-pair writes).
// ---------------------------------------------------------------------------
__global__ void k_scan(const int* __restrict__ lim) {
    __shared__ int sc[NITEMS];
    int i = threadIdx.x;
    bool is64 = (lim[1] == 0);
    int L = get_limit(lim, is64, i + 1) - get_limit(lim, is64, i);
    int l = L, base = 0;
    for (int k = 0; k < 8; k++) {
        int pr = l >> 1;
        sc[i] = pr;
        __syncthreads();
        for (int off = 1; off < NITEMS; off <<= 1) {
            int v = sc[i];
            int w = (i >= off) ? sc[i - off] : 0;
            __syncthreads();
            sc[i] = v + w;
            __syncthreads();
        }
        g_off[k * NITEMS + i] = sc[i] - pr;
        if (i == 0) { g_count[k] = sc[NITEMS - 1]; g_base[k] = base; }
        base += sc[NITEMS - 1];
        l = (l + 1) >> 1;
        __syncthreads();
    }
}

// ---------------------------------------------------------------------------
// Fill pair lists in parallel: one block per item.
// ---------------------------------------------------------------------------
__global__ void k_fill(const int* __restrict__ lim) {
    int item = blockIdx.x;
    bool is64 = (lim[1] == 0);
    int L = get_limit(lim, is64, item + 1) - get_limit(lim, is64, item);
    int s = 0, l = L;
    int rowb = item * ROWS_PER_ITEM;
    for (int k = 0; k < 8; k++) {
        int pr = l >> 1;
        int e = g_base[k] + g_off[k * NITEMS + item];
        for (int p = threadIdx.x; p < pr; p += blockDim.x) {
            g_src[e + p] = rowb + s + 2 * p;
            g_dst[e + p] = rowb + s + l + p;
        }
        s += 2 * pr;
        l = (l + 1) >> 1;
    }
}

// ---------------------------------------------------------------------------
// Level kernel, template on pairs-per-tile.
// X/H stored transposed in smem: Xs_t[i][row], pitch RPAD = PT+2 (even).
// f32x2 lanes = (row 2r, row 2r+1). W read pre-duplicated from global.
// 256 threads: tx = tid&63 (cols c = tx + 64*j), ty = tid>>6 (rowpair groups).
// ---------------------------------------------------------------------------
extern __shared__ float dyn_smem[];

template<int PT>
__global__ void __launch_bounds__(256, (PT == 32) ? 2 : ((PT == 16) ? 3 : 4))
k_level(const float* __restrict__ b1, const float* __restrict__ b2,
        const float* __restrict__ lnw, const float* __restrict__ lnb,
        int level)
{
    constexpr int RPAD = PT + 2;      // even pitch -> b64-aligned row pairs
    constexpr int RPT  = PT / 8;      // rowpairs per ty group
    constexpr int YP   = 132;         // Y pitch (row-major)

    int cnt  = g_count[level];
    int base = g_base[level];
    int j0 = blockIdx.x * PT;
    if (j0 >= cnt) return;
    int np = min(PT, cnt - j0);

    float* Xs = dyn_smem;                  // [256][RPAD] transposed; reused as Ys
    float* Hs = dyn_smem + 256 * RPAD;     // [256][RPAD] transposed

    int tid = threadIdx.x;
    int warp = tid >> 5, lane = tid & 31;

    // ---- Gather X transposed (coalesced LDG.32, 2-way-max STS conflicts) ----
    #pragma unroll
    for (int k = 0; k < PT; k++) {
        int seg = k * 8 + warp;            // [0, 8*PT)
        int row = seg >> 3;                // pair-row
        int i0  = (seg & 7) * 32;
        int q = (row < np) ? row : 0;
        int srow = g_src[base + j0 + q];
        int i = i0 + lane;
        float v = g_buf[(long)(srow + (i >> 7)) * DIM + (i & 127)];
        Xs[i * RPAD + row] = v;
    }
    __syncthreads();

    int tx = tid & 63, ty = tid >> 6;

    // ---- GEMM1: H = relu(X @ W1 + b1) ----
    {
        ull acc[RPT][4];
        #pragma unroll
        for (int j = 0; j < 4; j++) {
            ull bb = bcast2(b1[tx + 64 * j]);
            #pragma unroll
            for (int u = 0; u < RPT; u++) acc[u][j] = bb;
        }
        #pragma unroll 4
        for (int i = 0; i < 256; i++) {
            ull w[4];
            #pragma unroll
            for (int j = 0; j < 4; j++)
                w[j] = *(const ull*)&g_W1d[i * 256 + tx + 64 * j];
            ull xp[RPT];
            #pragma unroll
            for (int u = 0; u < RPT; u++)
                xp[u] = *(const ull*)&Xs[i * RPAD + 2 * (ty * RPT + u)];
            #pragma unroll
            for (int u = 0; u < RPT; u++)
                #pragma unroll
                for (int j = 0; j < 4; j++)
                    acc[u][j] = ffma2(xp[u], w[j], acc[u][j]);
        }
        #pragma unroll
        for (int u = 0; u < RPT; u++) {
            int row = 2 * (ty * RPT + u);
            #pragma unroll
            for (int j = 0; j < 4; j++) {
                int c = tx + 64 * j;
                float2 h = unpack2(acc[u][j]);
                h.x = fmaxf(h.x, 0.f); h.y = fmaxf(h.y, 0.f);
                *(ull*)&Hs[c * RPAD + row] = pack2(h.x, h.y);
            }
        }
    }
    __syncthreads();

    // ---- GEMM2: Y = H @ W2 + b2 (write row-major into Xs region) ----
    {
        ull acc[RPT][2];
        #pragma unroll
        for (int j = 0; j < 2; j++) {
            ull bb = bcast2(b2[tx + 64 * j]);
            #pragma unroll
            for (int u = 0; u < RPT; u++) acc[u][j] = bb;
        }
        #pragma unroll 4
        for (int i = 0; i < 256; i++) {
            ull w[2];
            #pragma unroll
            for (int j = 0; j < 2; j++)
                w[j] = *(const ull*)&g_W2d[i * 128 + tx + 64 * j];
            ull hp[RPT];
            #pragma unroll
            for (int u = 0; u < RPT; u++)
                hp[u] = *(const ull*)&Hs[i * RPAD + 2 * (ty * RPT + u)];
            #pragma unroll
            for (int u = 0; u < RPT; u++)
                #pragma unroll
                for (int j = 0; j < 2; j++)
                    acc[u][j] = ffma2(hp[u], w[j], acc[u][j]);
        }
        float* Ys = Xs;   // Xs no longer read after first __syncthreads
        #pragma unroll
        for (int u = 0; u < RPT; u++) {
            int row = 2 * (ty * RPT + u);
            #pragma unroll
            for (int j = 0; j < 2; j++) {
                int c = tx + 64 * j;
                float2 y = unpack2(acc[u][j]);
                Ys[row * YP + c]       = y.x;
                Ys[(row + 1) * YP + c] = y.y;
            }
        }
    }
    __syncthreads();

    // ---- LayerNorm per row + scatter to dst rows ----
    {
        constexpr int RPW = PT / 8;   // rows per warp
        const float* Ys = Xs;
        float4* gb4w = (float4*)g_buf;
        #pragma unroll
        for (int rr = 0; rr < RPW; rr++) {
            int row = warp * RPW + rr;
            int d = (row < np) ? g_dst[base + j0 + row] : -1;
            float4 y = *(const float4*)&Ys[row * YP + 4 * lane];
            float sum = y.x + y.y + y.z + y.w;
            float sq  = y.x * y.x + y.y * y.y + y.z * y.z + y.w * y.w;
            #pragma unroll
            for (int o = 16; o > 0; o >>= 1) {
                sum += __shfl_xor_sync(0xFFFFFFFFu, sum, o);
                sq  += __shfl_xor_sync(0xFFFFFFFFu, sq, o);
            }
            float mu  = sum * (1.f / 128.f);
            float var = sq * (1.f / 128.f) - mu * mu;
            float rs  = rsqrtf(var + 1e-5f);
            float4 wv = ((const float4*)lnw)[lane];
            float4 bv = ((const float4*)lnb)[lane];
            float4 o;
            o.x = (y.x - mu) * rs * wv.x + bv.x;
            o.y = (y.y - mu) * rs * wv.y + bv.y;
            o.z = (y.z - mu) * rs * wv.z + bv.z;
            o.w = (y.w - mu) * rs * wv.w + bv.w;
            if (d >= 0) gb4w[(long)d * 32 + lane] = o;
        }
    }
}

// ---------------------------------------------------------------------------
__global__ void k_gather(float* __restrict__ out, const int* __restrict__ lim) {
    int item = blockIdx.x;
    bool is64 = (lim[1] == 0);
    int L = get_limit(lim, is64, item + 1) - get_limit(lim, is64, item);
    const float* src = g_buf + ((long)item * ROWS_PER_ITEM + (2 * L - 2)) * DIM;
    out[item * DIM + threadIdx.x] = src[threadIdx.x];
}

// ---------------------------------------------------------------------------
extern "C" void kernel_launch(void* const* d_in, const int* in_sizes, int n_in,
                              void* d_out, int out_size) {
    const float* args = (const float*)d_in[0];
    const int*   lim  = (const int*)d_in[1];
    const float* W1   = (const float*)d_in[2];
    const float* b1   = (const float*)d_in[3];
    const float* W2   = (const float*)d_in[4];
    const float* b2   = (const float*)d_in[5];
    const float* lnw  = (const float*)d_in[6];
    const float* lnb  = (const float*)d_in[7];
    float* out = (float*)d_out;
    (void)in_sizes; (void)n_in; (void)out_size;

    const int smem32 = 2 * 256 * 34 * 4;   // 69632
    const int smem16 = 2 * 256 * 18 * 4;   // 36864
    const int smem8  = 2 * 256 * 10 * 4;   // 20480
    cudaFuncSetAttribute(k_level<32>, cudaFuncAttributeMaxDynamicSharedMemorySize, smem32);
    cudaFuncSetAttribute(k_level<16>, cudaFuncAttributeMaxDynamicSharedMemorySize, smem16);
    cudaFuncSetAttribute(k_level<8>,  cudaFuncAttributeMaxDynamicSharedMemorySize, smem8);

    k_wdup<<<256, 256>>>(W1, W2);
    dim3 gsc(2, NITEMS);
    k_scatter<<<gsc, 256>>>(args, lim);
    k_scan<<<1, NITEMS>>>(lim);
    k_fill<<<NITEMS, 128>>>(lim);

    for (int k = 0; k < 8; k++) {
        int maxpairs = NITEMS * (MAXM >> (k + 1));  // worst case; CTAs early-exit
        if (k <= 2) {
            int ctas = (maxpairs + 31) / 32;
            k_level<32><<<ctas, 256, smem32>>>(b1, b2, lnw, lnb, k);
        } else if (k == 3) {
            int ctas = (maxpairs + 15) / 16;
            k_level<16><<<ctas, 256, smem16>>>(b1, b2, lnw, lnb, k);
        } else {
            int ctas = (maxpairs + 7) / 8;
            k_level<8><<<ctas, 256, smem8>>>(b1, b2, lnw, lnb, k);
        }
    }

    k_gather<<<NITEMS, DIM>>>(out, lim);
}

// round 5
// speedup vs baseline: 1.0016x; 1.0016x over previous
#include <cuda_runtime.h>

#define NITEMS 512
#define MAXM   256
#define DIM    128
#define ROWS_PER_ITEM 512
#define MAXPAIRS 131072

// Tree scratch: 512 items * 512 rows * 128 floats = 128 MB
__device__ float g_buf[(long)NITEMS * ROWS_PER_ITEM * DIM];
// Duplicated weights for f32x2 row-pair math: W*d[i][c] = (w, w)
__device__ float2 g_W1d[256 * 256];   // 512 KB
__device__ float2 g_W2d[256 * 128];   // 256 KB
// Batched pair lists
__device__ int g_src[MAXPAIRS];
__device__ int g_dst[MAXPAIRS];
__device__ int g_off[8 * NITEMS];
__device__ int g_count[8];
__device__ int g_base[8];

typedef unsigned long long ull;

__device__ __forceinline__ ull ffma2(ull a, ull b, ull c) {
    ull d; asm("fma.rn.f32x2 %0, %1, %2, %3;" : "=l"(d) : "l"(a), "l"(b), "l"(c));
    return d;
}
__device__ __forceinline__ ull bcast2(float x) {
    ull d; asm("mov.b64 %0, {%1, %1};" : "=l"(d) : "f"(x)); return d;
}
__device__ __forceinline__ ull pack2(float x, float y) {
    ull d; asm("mov.b64 %0, {%1, %2};" : "=l"(d) : "f"(x), "f"(y)); return d;
}
__device__ __forceinline__ float2 unpack2(ull v) {
    float2 r; asm("mov.b64 {%0, %1}, %2;" : "=f"(r.x), "=f"(r.y) : "l"(v)); return r;
}
__device__ __forceinline__ int get_limit(const int* lim, bool is64, int i) {
    return is64 ? lim[2 * i] : lim[i];
}

// ---------------------------------------------------------------------------
__global__ void k_wdup(const float* __restrict__ W1, const float* __restrict__ W2) {
    int i = blockIdx.x, c = threadIdx.x;
    float w = W1[i * 256 + c];
    g_W1d[i * 256 + c] = make_float2(w, w);
    if (c < 128) {
        float v = W2[i * 128 + c];
        g_W2d[i * 128 + c] = make_float2(v, v);
    }
}

// ---------------------------------------------------------------------------
__global__ void k_scatter(const float* __restrict__ args, const int* __restrict__ lim) {
    int item = blockIdx.y;
    bool is64 = (lim[1] == 0);
    int start = get_limit(lim, is64, item);
    int L     = get_limit(lim, is64, item + 1) - start;
    int row0  = blockIdx.x * 128;
    int nrows = min(128, L - row0);
    if (nrows <= 0) return;
    const float4* src = (const float4*)(args + (long)(start + row0) * DIM);
    float4* dst = (float4*)(g_buf + ((long)item * ROWS_PER_ITEM + row0) * DIM);
    int total = nrows * (DIM / 4);
    for (int f = threadIdx.x; f < total; f += blockDim.x) dst[f] = src[f];
}

// ---------------------------------------------------------------------------
// Scan: per-level totals + per-item exclusive offsets (no per-pair writes).
// ---------------------------------------------------------------------------
__global__ void k_scan(const int* __restrict__ lim) {
    __shared__ int sc[NITEMS];
    int i = threadIdx.x;
    bool is64 = (lim[1] == 0);
    int L = get_limit(lim, is64, i + 1) - get_limit(lim, is64, i);
    int l = L, base = 0;
    for (int k = 0; k < 8; k++) {
        int pr = l >> 1;
        sc[i] = pr;
        __syncthreads();
        for (int off = 1; off < NITEMS; off <<= 1) {
            int v = sc[i];
            int w = (i >= off) ? sc[i - off] : 0;
            __syncthreads();
            sc[i] = v + w;
            __syncthreads();
        }
        g_off[k * NITEMS + i] = sc[i] - pr;
        if (i == 0) { g_count[k] = sc[NITEMS - 1]; g_base[k] = base; }
        base += sc[NITEMS - 1];
        l = (l + 1) >> 1;
        __syncthreads();
    }
}

// ---------------------------------------------------------------------------
// Fill pair lists in parallel: one block per item.
// ---------------------------------------------------------------------------
__global__ void k_fill(const int* __restrict__ lim) {
    int item = blockIdx.x;
    bool is64 = (lim[1] == 0);
    int L = get_limit(lim, is64, item + 1) - get_limit(lim, is64, item);
    int s = 0, l = L;
    int rowb = item * ROWS_PER_ITEM;
    for (int k = 0; k < 8; k++) {
        int pr = l >> 1;
        int e = g_base[k] + g_off[k * NITEMS + item];
        for (int p = threadIdx.x; p < pr; p += blockDim.x) {
            g_src[e + p] = rowb + s + 2 * p;
            g_dst[e + p] = rowb + s + l + p;
        }
        s += 2 * pr;
        l = (l + 1) >> 1;
    }
}

// ---------------------------------------------------------------------------
// Level kernel, template on pairs-per-tile.
// X/H stored transposed in smem: Xs_t[i][row], pitch RPAD = PT+2 (even).
// f32x2 lanes = (row 2r, row 2r+1). W read pre-duplicated from global.
// 256 threads: tx = tid&63 (cols c = tx + 64*j), ty = tid>>6 (rowpair groups).
// ---------------------------------------------------------------------------
extern __shared__ float dyn_smem[];

template<int PT>
__global__ void __launch_bounds__(256, (PT == 32) ? 2 : ((PT == 16) ? 3 : 4))
k_level(const float* __restrict__ b1, const float* __restrict__ b2,
        const float* __restrict__ lnw, const float* __restrict__ lnb,
        int level)
{
    constexpr int RPAD = PT + 2;      // even pitch -> b64-aligned row pairs
    constexpr int RPT  = PT / 8;      // rowpairs per ty group
    constexpr int YP   = 132;         // Y pitch (row-major)

    int cnt  = g_count[level];
    int base = g_base[level];
    int j0 = blockIdx.x * PT;
    if (j0 >= cnt) return;
    int np = min(PT, cnt - j0);

    float* Xs = dyn_smem;                  // [256][RPAD] transposed; reused as Ys
    float* Hs = dyn_smem + 256 * RPAD;     // [256][RPAD] transposed

    int tid = threadIdx.x;
    int warp = tid >> 5, lane = tid & 31;

    // ---- Gather X transposed (coalesced LDG.32, 2-way-max STS conflicts) ----
    #pragma unroll
    for (int k = 0; k < PT; k++) {
        int seg = k * 8 + warp;            // [0, 8*PT)
        int row = seg >> 3;                // pair-row
        int i0  = (seg & 7) * 32;
        int q = (row < np) ? row : 0;
        int srow = g_src[base + j0 + q];
        int i = i0 + lane;
        float v = g_buf[(long)(srow + (i >> 7)) * DIM + (i & 127)];
        Xs[i * RPAD + row] = v;
    }
    __syncthreads();

    int tx = tid & 63, ty = tid >> 6;

    // ---- GEMM1: H = relu(X @ W1 + b1) ----
    {
        ull acc[RPT][4];
        #pragma unroll
        for (int j = 0; j < 4; j++) {
            ull bb = bcast2(b1[tx + 64 * j]);
            #pragma unroll
            for (int u = 0; u < RPT; u++) acc[u][j] = bb;
        }
        #pragma unroll 4
        for (int i = 0; i < 256; i++) {
            ull w[4];
            #pragma unroll
            for (int j = 0; j < 4; j++)
                w[j] = *(const ull*)&g_W1d[i * 256 + tx + 64 * j];
            ull xp[RPT];
            #pragma unroll
            for (int u = 0; u < RPT; u++)
                xp[u] = *(const ull*)&Xs[i * RPAD + 2 * (ty * RPT + u)];
            #pragma unroll
            for (int u = 0; u < RPT; u++)
                #pragma unroll
                for (int j = 0; j < 4; j++)
                    acc[u][j] = ffma2(xp[u], w[j], acc[u][j]);
        }
        #pragma unroll
        for (int u = 0; u < RPT; u++) {
            int row = 2 * (ty * RPT + u);
            #pragma unroll
            for (int j = 0; j < 4; j++) {
                int c = tx + 64 * j;
                float2 h = unpack2(acc[u][j]);
                h.x = fmaxf(h.x, 0.f); h.y = fmaxf(h.y, 0.f);
                *(ull*)&Hs[c * RPAD + row] = pack2(h.x, h.y);
            }
        }
    }
    __syncthreads();

    // ---- GEMM2: Y = H @ W2 + b2 (write row-major into Xs region) ----
    {
        ull acc[RPT][2];
        #pragma unroll
        for (int j = 0; j < 2; j++) {
            ull bb = bcast2(b2[tx + 64 * j]);
            #pragma unroll
            for (int u = 0; u < RPT; u++) acc[u][j] = bb;
        }
        #pragma unroll 4
        for (int i = 0; i < 256; i++) {
            ull w[2];
            #pragma unroll
            for (int j = 0; j < 2; j++)
                w[j] = *(const ull*)&g_W2d[i * 128 + tx + 64 * j];
            ull hp[RPT];
            #pragma unroll
            for (int u = 0; u < RPT; u++)
                hp[u] = *(const ull*)&Hs[i * RPAD + 2 * (ty * RPT + u)];
            #pragma unroll
            for (int u = 0; u < RPT; u++)
                #pragma unroll
                for (int j = 0; j < 2; j++)
                    acc[u][j] = ffma2(hp[u], w[j], acc[u][j]);
        }
        float* Ys = Xs;   // Xs no longer read after first __syncthreads
        #pragma unroll
        for (int u = 0; u < RPT; u++) {
            int row = 2 * (ty * RPT + u);
            #pragma unroll
            for (int j = 0; j < 2; j++) {
                int c = tx + 64 * j;
                float2 y = unpack2(acc[u][j]);
                Ys[row * YP + c]       = y.x;
                Ys[(row + 1) * YP + c] = y.y;
            }
        }
    }
    __syncthreads();

    // ---- LayerNorm per row + scatter to dst rows ----
    {
        constexpr int RPW = PT / 8;   // rows per warp
        const float* Ys = Xs;
        float4* gb4w = (float4*)g_buf;
        #pragma unroll
        for (int rr = 0; rr < RPW; rr++) {
            int row = warp * RPW + rr;
            int d = (row < np) ? g_dst[base + j0 + row] : -1;
            float4 y = *(const float4*)&Ys[row * YP + 4 * lane];
            float sum = y.x + y.y + y.z + y.w;
            float sq  = y.x * y.x + y.y * y.y + y.z * y.z + y.w * y.w;
            #pragma unroll
            for (int o = 16; o > 0; o >>= 1) {
                sum += __shfl_xor_sync(0xFFFFFFFFu, sum, o);
                sq  += __shfl_xor_sync(0xFFFFFFFFu, sq, o);
            }
            float mu  = sum * (1.f / 128.f);
            float var = sq * (1.f / 128.f) - mu * mu;
            float rs  = rsqrtf(var + 1e-5f);
            float4 wv = ((const float4*)lnw)[lane];
            float4 bv = ((const float4*)lnb)[lane];
            float4 o;
            o.x = (y.x - mu) * rs * wv.x + bv.x;
            o.y = (y.y - mu) * rs * wv.y + bv.y;
            o.z = (y.z - mu) * rs * wv.z + bv.z;
            o.w = (y.w - mu) * rs * wv.w + bv.w;
            if (d >= 0) gb4w[(long)d * 32 + lane] = o;
        }
    }
}

// ---------------------------------------------------------------------------
__global__ void k_gather(float* __restrict__ out, const int* __restrict__ lim) {
    int item = blockIdx.x;
    bool is64 = (lim[1] == 0);
    int L = get_limit(lim, is64, item + 1) - get_limit(lim, is64, item);
    const float* src = g_buf + ((long)item * ROWS_PER_ITEM + (2 * L - 2)) * DIM;
    out[item * DIM + threadIdx.x] = src[threadIdx.x];
}

// ---------------------------------------------------------------------------
extern "C" void kernel_launch(void* const* d_in, const int* in_sizes, int n_in,
                              void* d_out, int out_size) {
    const float* args = (const float*)d_in[0];
    const int*   lim  = (const int*)d_in[1];
    const float* W1   = (const float*)d_in[2];
    const float* b1   = (const float*)d_in[3];
    const float* W2   = (const float*)d_in[4];
    const float* b2   = (const float*)d_in[5];
    const float* lnw  = (const float*)d_in[6];
    const float* lnb  = (const float*)d_in[7];
    float* out = (float*)d_out;
    (void)in_sizes; (void)n_in; (void)out_size;

    const int smem32 = 2 * 256 * 34 * 4;   // 69632
    const int smem16 = 2 * 256 * 18 * 4;   // 36864
    const int smem8  = 2 * 256 * 10 * 4;   // 20480
    cudaFuncSetAttribute(k_level<32>, cudaFuncAttributeMaxDynamicSharedMemorySize, smem32);
    cudaFuncSetAttribute(k_level<16>, cudaFuncAttributeMaxDynamicSharedMemorySize, smem16);
    cudaFuncSetAttribute(k_level<8>,  cudaFuncAttributeMaxDynamicSharedMemorySize, smem8);

    k_wdup<<<256, 256>>>(W1, W2);
    dim3 gsc(2, NITEMS);
    k_scatter<<<gsc, 256>>>(args, lim);
    k_scan<<<1, NITEMS>>>(lim);
    k_fill<<<NITEMS, 128>>>(lim);

    for (int k = 0; k < 8; k++) {
        int maxpairs = NITEMS * (MAXM >> (k + 1));  // worst case; CTAs early-exit
        if (k <= 2) {
            int ctas = (maxpairs + 31) / 32;
            k_level<32><<<ctas, 256, smem32>>>(b1, b2, lnw, lnb, k);
        } else if (k == 3) {
            int ctas = (maxpairs + 15) / 16;
            k_level<16><<<ctas, 256, smem16>>>(b1, b2, lnw, lnb, k);
        } else {
            int ctas = (maxpairs + 7) / 8;
            k_level<8><<<ctas, 256, smem8>>>(b1, b2, lnw, lnb, k);
        }
    }

    k_gather<<<NITEMS, DIM>>>(out, lim);
}

// round 8
// speedup vs baseline: 1.9234x; 1.9202x over previous
#include <cuda_runtime.h>
#include <cuda_bf16.h>
#include <stdint.h>

#define NITEMS 512
#define MAXM   256
#define DIM    128
#define RPI    512
#define MAXPAIRS 131072
#define TM     64
#define PITCHB 528           // smem row pitch in bytes (264 bf16)
#define XBYTES 33792         // 64 * 528

__device__ float          g_buf32[(long)NITEMS * RPI * DIM];
__device__ __nv_bfloat16  g_bufh [(long)NITEMS * RPI * DIM];
__device__ __nv_bfloat16  g_bufl [(long)NITEMS * RPI * DIM];
// Weight images pre-packed in mma.m16n8k16 B-fragment order:
// [kstep][ntile][lane] -> uint2 (reg b0, reg b1)
__device__ uint2 g_W1hi[16 * 32 * 32];
__device__ uint2 g_W1lo[16 * 32 * 32];
__device__ uint2 g_W2hi[16 * 16 * 32];
__device__ uint2 g_W2lo[16 * 16 * 32];
__device__ int g_src[MAXPAIRS];
__device__ int g_dst[MAXPAIRS];
__device__ int g_off[8 * NITEMS];
__device__ int g_count[8];
__device__ int g_base[8];

__device__ __forceinline__ int get_limit(const int* lim, bool is64, int i) {
    return is64 ? lim[2 * i] : lim[i];
}
__device__ __forceinline__ void split2(float v, unsigned short& h, unsigned short& l) {
    __nv_bfloat16 hb = __float2bfloat16(v);
    __nv_bfloat16 lb = __float2bfloat16(v - __bfloat162float(hb));
    h = __bfloat16_as_ushort(hb); l = __bfloat16_as_ushort(lb);
}
__device__ __forceinline__ uint32_t pk(unsigned short a, unsigned short b) {
    return (uint32_t)a | ((uint32_t)b << 16);
}
__device__ __forceinline__ uint32_t smem_u32(const void* p) {
    uint32_t a;
    asm("{ .reg .u64 t; cvta.to.shared.u64 t, %1; cvt.u32.u64 %0, t; }" : "=r"(a) : "l"(p));
    return a;
}
__device__ __forceinline__ void ldm4(uint32_t* a, uint32_t addr) {
    asm volatile("ldmatrix.sync.aligned.m8n8.x4.shared.b16 {%0,%1,%2,%3}, [%4];"
                 : "=r"(a[0]), "=r"(a[1]), "=r"(a[2]), "=r"(a[3]) : "r"(addr));
}
__device__ __forceinline__ void mma16816(float* c, const uint32_t* a, uint2 b) {
    asm volatile(
        "mma.sync.aligned.m16n8k16.row.col.f32.bf16.bf16.f32 "
        "{%0,%1,%2,%3}, {%4,%5,%6,%7}, {%8,%9}, {%0,%1,%2,%3};"
        : "+f"(c[0]), "+f"(c[1]), "+f"(c[2]), "+f"(c[3])
        : "r"(a[0]), "r"(a[1]), "r"(a[2]), "r"(a[3]), "r"(b.x), "r"(b.y));
}

// ---------------------------------------------------------------------------
// Weight prep: split to bf16 hi/lo and pack into B-fragment order.
// grid 64 x 256 threads: g = (kstep, ntile, lane)
// ---------------------------------------------------------------------------
__global__ void k_wprep(const float* __restrict__ W1, const float* __restrict__ W2) {
    int g = blockIdx.x * 256 + threadIdx.x;        // [0, 16384)
    int kstep = g >> 10, ntile = (g >> 5) & 31, lane = g & 31;
    int kb = kstep * 16 + (lane & 3) * 2;
    {
        int n = ntile * 8 + (lane >> 2);
        unsigned short h00, l00, h01, l01, h10, l10, h11, l11;
        split2(W1[kb * 256 + n],       h00, l00);
        split2(W1[(kb + 1) * 256 + n], h01, l01);
        split2(W1[(kb + 8) * 256 + n], h10, l10);
        split2(W1[(kb + 9) * 256 + n], h11, l11);
        int idx = (kstep * 32 + ntile) * 32 + lane;
        g_W1hi[idx] = make_uint2(pk(h00, h01), pk(h10, h11));
        g_W1lo[idx] = make_uint2(pk(l00, l01), pk(l10, l11));
    }
    if (ntile < 16) {
        int n = ntile * 8 + (lane >> 2);
        unsigned short h00, l00, h01, l01, h10, l10, h11, l11;
        split2(W2[kb * 128 + n],       h00, l00);
        split2(W2[(kb + 1) * 128 + n], h01, l01);
        split2(W2[(kb + 8) * 128 + n], h10, l10);
        split2(W2[(kb + 9) * 128 + n], h11, l11);
        int idx = (kstep * 16 + ntile) * 32 + lane;
        g_W2hi[idx] = make_uint2(pk(h00, h01), pk(h10, h11));
        g_W2lo[idx] = make_uint2(pk(l00, l01), pk(l10, l11));
    }
}

// ---------------------------------------------------------------------------
__global__ void k_scatter(const float* __restrict__ args, const int* __restrict__ lim) {
    int item = blockIdx.y;
    bool is64 = (lim[1] == 0);
    int start = get_limit(lim, is64, item);
    int L     = get_limit(lim, is64, item + 1) - start;
    int r0 = blockIdx.x * 64;
    int nrows = min(64, L - r0);
    if (nrows <= 0) return;
    const float* src = args + (long)(start + r0) * DIM;
    long dbase = ((long)item * RPI + r0) * DIM;
    int total = nrows * DIM;
    for (int i = threadIdx.x; i < total; i += blockDim.x) {
        float x = src[i];
        unsigned short h, l; split2(x, h, l);
        g_buf32[dbase + i] = x;
        g_bufh[dbase + i] = __ushort_as_bfloat16(h);
        g_bufl[dbase + i] = __ushort_as_bfloat16(l);
    }
}

// ---------------------------------------------------------------------------
__global__ void k_scan(const int* __restrict__ lim) {
    __shared__ int sc[NITEMS];
    int i = threadIdx.x;
    bool is64 = (lim[1] == 0);
    int L = get_limit(lim, is64, i + 1) - get_limit(lim, is64, i);
    int l = L, base = 0;
    for (int k = 0; k < 8; k++) {
        int pr = l >> 1;
        sc[i] = pr;
        __syncthreads();
        for (int off = 1; off < NITEMS; off <<= 1) {
            int v = sc[i];
            int w = (i >= off) ? sc[i - off] : 0;
            __syncthreads();
            sc[i] = v + w;
            __syncthreads();
        }
        g_off[k * NITEMS + i] = sc[i] - pr;
        if (i == 0) { g_count[k] = sc[NITEMS - 1]; g_base[k] = base; }
        base += sc[NITEMS - 1];
        l = (l + 1) >> 1;
        __syncthreads();
    }
}

__global__ void k_fill(const int* __restrict__ lim) {
    int item = blockIdx.x;
    bool is64 = (lim[1] == 0);
    int L = get_limit(lim, is64, item + 1) - get_limit(lim, is64, item);
    int s = 0, l = L;
    int rowb = item * RPI;
    for (int k = 0; k < 8; k++) {
        int pr = l >> 1;
        int e = g_base[k] + g_off[k * NITEMS + item];
        for (int p = threadIdx.x; p < pr; p += blockDim.x) {
            g_src[e + p] = rowb + s + 2 * p;
            g_dst[e + p] = rowb + s + l + p;
        }
        s += 2 * pr;
        l = (l + 1) >> 1;
    }
}

// ---------------------------------------------------------------------------
// Tensor level kernel: 64 pairs/CTA, 256 threads = 8 warps (2 M x 4 N).
// X/H as bf16 hi/lo images in smem (row-major, pitch 528B).
// 3-term split-bf16: (Ahi,Whi), (Ahi,Wlo), (Alo,Whi).
// ---------------------------------------------------------------------------
extern __shared__ __align__(16) unsigned char smraw[];

__global__ void __launch_bounds__(256, 2) k_level_mma(
    const float* __restrict__ b1, const float* __restrict__ b2,
    const float* __restrict__ lnw, const float* __restrict__ lnb, int level)
{
    int cnt = g_count[level], base = g_base[level];
    int j0 = blockIdx.x * TM;
    if (j0 >= cnt) return;
    int np = min(TM, cnt - j0);

    unsigned char* Xhi = smraw;
    unsigned char* Xlo = smraw + XBYTES;
    uint32_t XhiA = smem_u32(Xhi);
    uint32_t XloA = XhiA + XBYTES;

    int tid = threadIdx.x;
    int warp = tid >> 5, lane = tid & 31;
    int warp_m = warp & 1, warp_n = warp >> 1;

    // ---- Gather X: pair = 2 contiguous tree rows = 512B = 32 x uint4 ----
    {
        const uint4* sh = (const uint4*)g_bufh;
        const uint4* sl = (const uint4*)g_bufl;
        #pragma unroll
        for (int it = 0; it < 8; it++) {
            int f = it * 256 + tid;
            int r = f >> 5, q = f & 31;
            int rc = min(r, np - 1);
            int sr = g_src[base + j0 + rc];
            *(uint4*)(Xhi + r * PITCHB + q * 16) = sh[(long)sr * 16 + q];
            *(uint4*)(Xlo + r * PITCHB + q * 16) = sl[(long)sr * 16 + q];
        }
    }
    __syncthreads();

    int lrow = lane & 15;                       // ldmatrix row within 16-block
    int lcol = (lane >> 4) << 3;                // ldmatrix col offset (0 or 8)

    // ---- GEMM1: H[64,256] = X @ W1 (3-term), warp tile 32 x 64 ----
    float acc[2][8][4];
    #pragma unroll
    for (int rb = 0; rb < 2; rb++)
        #pragma unroll
        for (int nt = 0; nt < 8; nt++)
            #pragma unroll
            for (int e = 0; e < 4; e++) acc[rb][nt][e] = 0.f;

    #pragma unroll 1
    for (int term = 0; term < 3; term++) {
        uint32_t Aa = (term == 2) ? XloA : XhiA;
        const uint2* __restrict__ B = (term == 1) ? g_W1lo : g_W1hi;
        #pragma unroll 4
        for (int ks = 0; ks < 16; ks++) {
            uint32_t a0[4], a1[4];
            uint32_t col2 = (uint32_t)(ks * 16 + lcol) * 2;
            ldm4(a0, Aa + (uint32_t)(warp_m * 32 + lrow) * PITCHB + col2);
            ldm4(a1, Aa + (uint32_t)(warp_m * 32 + 16 + lrow) * PITCHB + col2);
            #pragma unroll
            for (int nt = 0; nt < 8; nt++) {
                uint2 b = B[(ks * 32 + warp_n * 8 + nt) * 32 + lane];
                mma16816(acc[0][nt], a0, b);
                mma16816(acc[1][nt], a1, b);
            }
        }
    }
    __syncthreads();   // all warps done reading X before H overwrites it

    // ---- Epilogue1: H = relu(acc + b1), split hi/lo into X images ----
    #pragma unroll
    for (int rb = 0; rb < 2; rb++) {
        int row = warp_m * 32 + rb * 16 + (lane >> 2);
        #pragma unroll
        for (int nt = 0; nt < 8; nt++) {
            int col = (warp_n * 8 + nt) * 8 + (lane & 3) * 2;
            float v0 = fmaxf(acc[rb][nt][0] + b1[col], 0.f);
            float v1 = fmaxf(acc[rb][nt][1] + b1[col + 1], 0.f);
            float v2 = fmaxf(acc[rb][nt][2] + b1[col], 0.f);
            float v3 = fmaxf(acc[rb][nt][3] + b1[col + 1], 0.f);
            unsigned short h0, l0, h1, l1, h2, l2, h3, l3;
            split2(v0, h0, l0); split2(v1, h1, l1);
            split2(v2, h2, l2); split2(v3, h3, l3);
            *(uint32_t*)(Xhi + row * PITCHB + col * 2)       = pk(h0, h1);
            *(uint32_t*)(Xlo + row * PITCHB + col * 2)       = pk(l0, l1);
            *(uint32_t*)(Xhi + (row + 8) * PITCHB + col * 2) = pk(h2, h3);
            *(uint32_t*)(Xlo + (row + 8) * PITCHB + col * 2) = pk(l2, l3);
        }
    }
    __syncthreads();

    // ---- GEMM2: Y[64,128] = H @ W2 (3-term), warp tile 32 x 32 ----
    float acc2[2][4][4];
    #pragma unroll
    for (int rb = 0; rb < 2; rb++)
        #pragma unroll
        for (int nt = 0; nt < 4; nt++)
            #pragma unroll
            for (int e = 0; e < 4; e++) acc2[rb][nt][e] = 0.f;

    #pragma unroll 1
    for (int term = 0; term < 3; term++) {
        uint32_t Aa = (term == 2) ? XloA : XhiA;
        const uint2* __restrict__ B = (term == 1) ? g_W2lo : g_W2hi;
        #pragma unroll 4
        for (int ks = 0; ks < 16; ks++) {
            uint32_t a0[4], a1[4];
            uint32_t col2 = (uint32_t)(ks * 16 + lcol) * 2;
            ldm4(a0, Aa + (uint32_t)(warp_m * 32 + lrow) * PITCHB + col2);
            ldm4(a1, Aa + (uint32_t)(warp_m * 32 + 16 + lrow) * PITCHB + col2);
            #pragma unroll
            for (int nt = 0; nt < 4; nt++) {
                uint2 b = B[(ks * 16 + warp_n * 4 + nt) * 32 + lane];
                mma16816(acc2[0][nt], a0, b);
                mma16816(acc2[1][nt], a1, b);
            }
        }
    }
    __syncthreads();   // all warps done reading H before Y overwrites

    // ---- Epilogue2a: Y = acc2 + b2 -> f32 smem [64][132] ----
    float* Ys = (float*)Xhi;
    #pragma unroll
    for (int rb = 0; rb < 2; rb++) {
        int row = warp_m * 32 + rb * 16 + (lane >> 2);
        #pragma unroll
        for (int nt = 0; nt < 4; nt++) {
            int col = (warp_n * 4 + nt) * 8 + (lane & 3) * 2;
            *(float2*)(Ys + row * 132 + col) =
                make_float2(acc2[rb][nt][0] + b2[col], acc2[rb][nt][1] + b2[col + 1]);
            *(float2*)(Ys + (row + 8) * 132 + col) =
                make_float2(acc2[rb][nt][2] + b2[col], acc2[rb][nt][3] + b2[col + 1]);
        }
    }
    __syncthreads();

    // ---- Epilogue2b: LayerNorm per row + store to tree buffers ----
    #pragma unroll
    for (int rr = 0; rr < 8; rr++) {
        int row = warp * 8 + rr;
        int d = (row < np) ? g_dst[base + j0 + row] : -1;
        float4 y = *(const float4*)(Ys + row * 132 + lane * 4);
        float sum = y.x + y.y + y.z + y.w;
        float sq  = y.x * y.x + y.y * y.y + y.z * y.z + y.w * y.w;
        #pragma unroll
        for (int o = 16; o > 0; o >>= 1) {
            sum += __shfl_xor_sync(0xFFFFFFFFu, sum, o);
            sq  += __shfl_xor_sync(0xFFFFFFFFu, sq, o);
        }
        float mu  = sum * (1.f / 128.f);
        float var = sq * (1.f / 128.f) - mu * mu;
        float rs  = rsqrtf(var + 1e-5f);
        float4 wv = ((const float4*)lnw)[lane];
        float4 bv = ((const float4*)lnb)[lane];
        float4 o;
        o.x = (y.x - mu) * rs * wv.x + bv.x;
        o.y = (y.y - mu) * rs * wv.y + bv.y;
        o.z = (y.z - mu) * rs * wv.z + bv.z;
        o.w = (y.w - mu) * rs * wv.w + bv.w;
        if (d >= 0) {
            ((float4*)g_buf32)[(long)d * 32 + lane] = o;
            unsigned short h0, l0, h1, l1, h2, l2, h3, l3;
            split2(o.x, h0, l0); split2(o.y, h1, l1);
            split2(o.z, h2, l2); split2(o.w, h3, l3);
            ((uint2*)g_bufh)[(long)d * 32 + lane] = make_uint2(pk(h0, h1), pk(h2, h3));
            ((uint2*)g_bufl)[(long)d * 32 + lane] = make_uint2(pk(l0, l1), pk(l2, l3));
        }
    }
}

// ---------------------------------------------------------------------------
__global__ void k_gather(float* __restrict__ out, const int* __restrict__ lim) {
    int item = blockIdx.x;
    bool is64 = (lim[1] == 0);
    int L = get_limit(lim, is64, item + 1) - get_limit(lim, is64, item);
    const float* src = g_buf32 + ((long)item * RPI + (2 * L - 2)) * DIM;
    out[item * DIM + threadIdx.x] = src[threadIdx.x];
}

// ---------------------------------------------------------------------------
extern "C" void kernel_launch(void* const* d_in, const int* in_sizes, int n_in,
                              void* d_out, int out_size) {
    const float* args = (const float*)d_in[0];
    const int*   lim  = (const int*)d_in[1];
    const float* W1   = (const float*)d_in[2];
    const float* b1   = (const float*)d_in[3];
    const float* W2   = (const float*)d_in[4];
    const float* b2   = (const float*)d_in[5];
    const float* lnw  = (const float*)d_in[6];
    const float* lnb  = (const float*)d_in[7];
    float* out = (float*)d_out;
    (void)in_sizes; (void)n_in; (void)out_size;

    cudaFuncSetAttribute(k_level_mma, cudaFuncAttributeMaxDynamicSharedMemorySize, 2 * XBYTES);

    k_wprep<<<64, 256>>>(W1, W2);
    dim3 gsc(4, NITEMS);
    k_scatter<<<gsc, 256>>>(args, lim);
    k_scan<<<1, NITEMS>>>(lim);
    k_fill<<<NITEMS, 128>>>(lim);

    for (int k = 0; k < 8; k++) {
        int mp = NITEMS * (MAXM >> (k + 1));
        if (mp < NITEMS) mp = NITEMS;
        int ctas = (mp + TM - 1) / TM;
        k_level_mma<<<ctas, 256, 2 * XBYTES>>>(b1, b2, lnw, lnb, k);
    }

    k_gather<<<NITEMS, DIM>>>(out, lim);
}

// round 9
// speedup vs baseline: 1.9595x; 1.0188x over previous
#include <cuda_runtime.h>
#include <cuda_bf16.h>
#include <stdint.h>

#define NITEMS 512
#define MAXM   256
#define DIM    128
#define RPI    512
#define MAXPAIRS 131072
#define TM     64
#define PITCHB 528           // smem row pitch in bytes (264 bf16)
#define XBYTES 33792         // 64 * 528

__device__ __nv_bfloat16  g_bufh [(long)NITEMS * RPI * DIM];
__device__ __nv_bfloat16  g_bufl [(long)NITEMS * RPI * DIM];
// Weight images pre-packed in mma.m16n8k16 B-fragment order:
// [kstep][ntile][lane] -> uint2 (reg b0, reg b1)
__device__ uint2 g_W1hi[16 * 32 * 32];
__device__ uint2 g_W1lo[16 * 32 * 32];
__device__ uint2 g_W2hi[16 * 16 * 32];
__device__ uint2 g_W2lo[16 * 16 * 32];
__device__ int g_src[MAXPAIRS];
__device__ int g_dst[MAXPAIRS];
__device__ int g_off[4 * NITEMS];
__device__ int g_count[4];
__device__ int g_base[4];

__device__ __forceinline__ int get_limit(const int* lim, bool is64, int i) {
    return is64 ? lim[2 * i] : lim[i];
}
__device__ __forceinline__ void split2(float v, unsigned short& h, unsigned short& l) {
    __nv_bfloat16 hb = __float2bfloat16(v);
    __nv_bfloat16 lb = __float2bfloat16(v - __bfloat162float(hb));
    h = __bfloat16_as_ushort(hb); l = __bfloat16_as_ushort(lb);
}
__device__ __forceinline__ uint32_t pk(unsigned short a, unsigned short b) {
    return (uint32_t)a | ((uint32_t)b << 16);
}
__device__ __forceinline__ uint32_t smem_u32(const void* p) {
    uint32_t a;
    asm("{ .reg .u64 t; cvta.to.shared.u64 t, %1; cvt.u32.u64 %0, t; }" : "=r"(a) : "l"(p));
    return a;
}
__device__ __forceinline__ void ldm4(uint32_t* a, uint32_t addr) {
    asm volatile("ldmatrix.sync.aligned.m8n8.x4.shared.b16 {%0,%1,%2,%3}, [%4];"
                 : "=r"(a[0]), "=r"(a[1]), "=r"(a[2]), "=r"(a[3]) : "r"(addr));
}
__device__ __forceinline__ void mma16816(float* c, const uint32_t* a, uint2 b) {
    asm volatile(
        "mma.sync.aligned.m16n8k16.row.col.f32.bf16.bf16.f32 "
        "{%0,%1,%2,%3}, {%4,%5,%6,%7}, {%8,%9}, {%0,%1,%2,%3};"
        : "+f"(c[0]), "+f"(c[1]), "+f"(c[2]), "+f"(c[3])
        : "r"(a[0]), "r"(a[1]), "r"(a[2]), "r"(a[3]), "r"(b.x), "r"(b.y));
}

// ---------------------------------------------------------------------------
// Weight prep: split to bf16 hi/lo and pack into B-fragment order.
// ---------------------------------------------------------------------------
__global__ void k_wprep(const float* __restrict__ W1, const float* __restrict__ W2) {
    int g = blockIdx.x * 256 + threadIdx.x;        // [0, 16384)
    int kstep = g >> 10, ntile = (g >> 5) & 31, lane = g & 31;
    int kb = kstep * 16 + (lane & 3) * 2;
    {
        int n = ntile * 8 + (lane >> 2);
        unsigned short h00, l00, h01, l01, h10, l10, h11, l11;
        split2(W1[kb * 256 + n],       h00, l00);
        split2(W1[(kb + 1) * 256 + n], h01, l01);
        split2(W1[(kb + 8) * 256 + n], h10, l10);
        split2(W1[(kb + 9) * 256 + n], h11, l11);
        int idx = (kstep * 32 + ntile) * 32 + lane;
        g_W1hi[idx] = make_uint2(pk(h00, h01), pk(h10, h11));
        g_W1lo[idx] = make_uint2(pk(l00, l01), pk(l10, l11));
    }
    if (ntile < 16) {
        int n = ntile * 8 + (lane >> 2);
        unsigned short h00, l00, h01, l01, h10, l10, h11, l11;
        split2(W2[kb * 128 + n],       h00, l00);
        split2(W2[(kb + 1) * 128 + n], h01, l01);
        split2(W2[(kb + 8) * 128 + n], h10, l10);
        split2(W2[(kb + 9) * 128 + n], h11, l11);
        int idx = (kstep * 16 + ntile) * 32 + lane;
        g_W2hi[idx] = make_uint2(pk(h00, h01), pk(h10, h11));
        g_W2lo[idx] = make_uint2(pk(l00, l01), pk(l10, l11));
    }
}

// ---------------------------------------------------------------------------
__global__ void k_scatter(const float* __restrict__ args, const int* __restrict__ lim) {
    int item = blockIdx.y;
    bool is64 = (lim[1] == 0);
    int start = get_limit(lim, is64, item);
    int L     = get_limit(lim, is64, item + 1) - start;
    int r0 = blockIdx.x * 64;
    int nrows = min(64, L - r0);
    if (nrows <= 0) return;
    const float* src = args + (long)(start + r0) * DIM;
    long dbase = ((long)item * RPI + r0) * DIM;
    int total = nrows * DIM;
    for (int i = threadIdx.x; i < total; i += blockDim.x) {
        float x = src[i];
        unsigned short h, l; split2(x, h, l);
        g_bufh[dbase + i] = __ushort_as_bfloat16(h);
        g_bufl[dbase + i] = __ushort_as_bfloat16(l);
    }
}

// ---------------------------------------------------------------------------
// Scan + fill: batched pair lists for levels 0..3 only.
// ---------------------------------------------------------------------------
__global__ void k_scan(const int* __restrict__ lim) {
    __shared__ int sc[NITEMS];
    int i = threadIdx.x;
    bool is64 = (lim[1] == 0);
    int L = get_limit(lim, is64, i + 1) - get_limit(lim, is64, i);
    int l = L, base = 0;
    for (int k = 0; k < 4; k++) {
        int pr = l >> 1;
        sc[i] = pr;
        __syncthreads();
        for (int off = 1; off < NITEMS; off <<= 1) {
            int v = sc[i];
            int w = (i >= off) ? sc[i - off] : 0;
            __syncthreads();
            sc[i] = v + w;
            __syncthreads();
        }
        g_off[k * NITEMS + i] = sc[i] - pr;
        if (i == 0) { g_count[k] = sc[NITEMS - 1]; g_base[k] = base; }
        base += sc[NITEMS - 1];
        l = (l + 1) >> 1;
        __syncthreads();
    }
}

__global__ void k_fill(const int* __restrict__ lim) {
    int item = blockIdx.x;
    bool is64 = (lim[1] == 0);
    int L = get_limit(lim, is64, item + 1) - get_limit(lim, is64, item);
    int s = 0, l = L;
    int rowb = item * RPI;
    for (int k = 0; k < 4; k++) {
        int pr = l >> 1;
        int e = g_base[k] + g_off[k * NITEMS + item];
        for (int p = threadIdx.x; p < pr; p += blockDim.x) {
            g_src[e + p] = rowb + s + 2 * p;
            g_dst[e + p] = rowb + s + l + p;
        }
        s += 2 * pr;
        l = (l + 1) >> 1;
    }
}

// ---------------------------------------------------------------------------
// Batched level kernel (levels 0..3): 64 pairs/CTA, 8 warps (2 M x 4 N).
// ---------------------------------------------------------------------------
extern __shared__ __align__(16) unsigned char smraw[];

__global__ void __launch_bounds__(256, 2) k_level_mma(
    const float* __restrict__ b1, const float* __restrict__ b2,
    const float* __restrict__ lnw, const float* __restrict__ lnb, int level)
{
    int cnt = g_count[level], base = g_base[level];
    int j0 = blockIdx.x * TM;
    if (j0 >= cnt) return;
    int np = min(TM, cnt - j0);

    unsigned char* Xhi = smraw;
    unsigned char* Xlo = smraw + XBYTES;
    uint32_t XhiA = smem_u32(Xhi);
    uint32_t XloA = XhiA + XBYTES;

    int tid = threadIdx.x;
    int warp = tid >> 5, lane = tid & 31;
    int warp_m = warp & 1, warp_n = warp >> 1;

    {
        const uint4* sh = (const uint4*)g_bufh;
        const uint4* sl = (const uint4*)g_bufl;
        #pragma unroll
        for (int it = 0; it < 8; it++) {
            int f = it * 256 + tid;
            int r = f >> 5, q = f & 31;
            int rc = min(r, np - 1);
            int sr = g_src[base + j0 + rc];
            *(uint4*)(Xhi + r * PITCHB + q * 16) = sh[(long)sr * 16 + q];
            *(uint4*)(Xlo + r * PITCHB + q * 16) = sl[(long)sr * 16 + q];
        }
    }
    __syncthreads();

    int lrow = lane & 15;
    int lcol = (lane >> 4) << 3;

    // ---- GEMM1 ----
    float acc[2][8][4];
    #pragma unroll
    for (int rb = 0; rb < 2; rb++)
        #pragma unroll
        for (int nt = 0; nt < 8; nt++)
            #pragma unroll
            for (int e = 0; e < 4; e++) acc[rb][nt][e] = 0.f;

    #pragma unroll 1
    for (int term = 0; term < 3; term++) {
        uint32_t Aa = (term == 2) ? XloA : XhiA;
        const uint2* __restrict__ B = (term == 1) ? g_W1lo : g_W1hi;
        #pragma unroll 4
        for (int ks = 0; ks < 16; ks++) {
            uint32_t a0[4], a1[4];
            uint32_t col2 = (uint32_t)(ks * 16 + lcol) * 2;
            ldm4(a0, Aa + (uint32_t)(warp_m * 32 + lrow) * PITCHB + col2);
            ldm4(a1, Aa + (uint32_t)(warp_m * 32 + 16 + lrow) * PITCHB + col2);
            #pragma unroll
            for (int nt = 0; nt < 8; nt++) {
                uint2 b = B[(ks * 32 + warp_n * 8 + nt) * 32 + lane];
                mma16816(acc[0][nt], a0, b);
                mma16816(acc[1][nt], a1, b);
            }
        }
    }
    __syncthreads();

    // ---- Epilogue1: H = relu(acc + b1) -> X images ----
    #pragma unroll
    for (int rb = 0; rb < 2; rb++) {
        int row = warp_m * 32 + rb * 16 + (lane >> 2);
        #pragma unroll
        for (int nt = 0; nt < 8; nt++) {
            int col = (warp_n * 8 + nt) * 8 + (lane & 3) * 2;
            float v0 = fmaxf(acc[rb][nt][0] + b1[col], 0.f);
            float v1 = fmaxf(acc[rb][nt][1] + b1[col + 1], 0.f);
            float v2 = fmaxf(acc[rb][nt][2] + b1[col], 0.f);
            float v3 = fmaxf(acc[rb][nt][3] + b1[col + 1], 0.f);
            unsigned short h0, l0, h1, l1, h2, l2, h3, l3;
            split2(v0, h0, l0); split2(v1, h1, l1);
            split2(v2, h2, l2); split2(v3, h3, l3);
            *(uint32_t*)(Xhi + row * PITCHB + col * 2)       = pk(h0, h1);
            *(uint32_t*)(Xlo + row * PITCHB + col * 2)       = pk(l0, l1);
            *(uint32_t*)(Xhi + (row + 8) * PITCHB + col * 2) = pk(h2, h3);
            *(uint32_t*)(Xlo + (row + 8) * PITCHB + col * 2) = pk(l2, l3);
        }
    }
    __syncthreads();

    // ---- GEMM2 ----
    float acc2[2][4][4];
    #pragma unroll
    for (int rb = 0; rb < 2; rb++)
        #pragma unroll
        for (int nt = 0; nt < 4; nt++)
            #pragma unroll
            for (int e = 0; e < 4; e++) acc2[rb][nt][e] = 0.f;

    #pragma unroll 1
    for (int term = 0; term < 3; term++) {
        uint32_t Aa = (term == 2) ? XloA : XhiA;
        const uint2* __restrict__ B = (term == 1) ? g_W2lo : g_W2hi;
        #pragma unroll 4
        for (int ks = 0; ks < 16; ks++) {
            uint32_t a0[4], a1[4];
            uint32_t col2 = (uint32_t)(ks * 16 + lcol) * 2;
            ldm4(a0, Aa + (uint32_t)(warp_m * 32 + lrow) * PITCHB + col2);
            ldm4(a1, Aa + (uint32_t)(warp_m * 32 + 16 + lrow) * PITCHB + col2);
            #pragma unroll
            for (int nt = 0; nt < 4; nt++) {
                uint2 b = B[(ks * 16 + warp_n * 4 + nt) * 32 + lane];
                mma16816(acc2[0][nt], a0, b);
                mma16816(acc2[1][nt], a1, b);
            }
        }
    }
    __syncthreads();

    // ---- Epilogue2a: Y -> f32 smem [64][132] ----
    float* Ys = (float*)Xhi;
    #pragma unroll
    for (int rb = 0; rb < 2; rb++) {
        int row = warp_m * 32 + rb * 16 + (lane >> 2);
        #pragma unroll
        for (int nt = 0; nt < 4; nt++) {
            int col = (warp_n * 4 + nt) * 8 + (lane & 3) * 2;
            *(float2*)(Ys + row * 132 + col) =
                make_float2(acc2[rb][nt][0] + b2[col], acc2[rb][nt][1] + b2[col + 1]);
            *(float2*)(Ys + (row + 8) * 132 + col) =
                make_float2(acc2[rb][nt][2] + b2[col], acc2[rb][nt][3] + b2[col + 1]);
        }
    }
    __syncthreads();

    // ---- Epilogue2b: LayerNorm + store hi/lo ----
    #pragma unroll
    for (int rr = 0; rr < 8; rr++) {
        int row = warp * 8 + rr;
        int d = (row < np) ? g_dst[base + j0 + row] : -1;
        float4 y = *(const float4*)(Ys + row * 132 + lane * 4);
        float sum = y.x + y.y + y.z + y.w;
        float sq  = y.x * y.x + y.y * y.y + y.z * y.z + y.w * y.w;
        #pragma unroll
        for (int o = 16; o > 0; o >>= 1) {
            sum += __shfl_xor_sync(0xFFFFFFFFu, sum, o);
            sq  += __shfl_xor_sync(0xFFFFFFFFu, sq, o);
        }
        float mu  = sum * (1.f / 128.f);
        float var = sq * (1.f / 128.f) - mu * mu;
        float rs  = rsqrtf(var + 1e-5f);
        float4 wv = ((const float4*)lnw)[lane];
        float4 bv = ((const float4*)lnb)[lane];
        float4 o;
        o.x = (y.x - mu) * rs * wv.x + bv.x;
        o.y = (y.y - mu) * rs * wv.y + bv.y;
        o.z = (y.z - mu) * rs * wv.z + bv.z;
        o.w = (y.w - mu) * rs * wv.w + bv.w;
        if (d >= 0) {
            unsigned short h0, l0, h1, l1, h2, l2, h3, l3;
            split2(o.x, h0, l0); split2(o.y, h1, l1);
            split2(o.z, h2, l2); split2(o.w, h3, l3);
            ((uint2*)g_bufh)[(long)d * 32 + lane] = make_uint2(pk(h0, h1), pk(h2, h3));
            ((uint2*)g_bufl)[(long)d * 32 + lane] = make_uint2(pk(l0, l1), pk(l2, l3));
        }
    }
}

// ---------------------------------------------------------------------------
// Finisher: one CTA per item handles tree levels 4..7 (l <= 16 rows, <= 8
// pairs per level). 8 warps spread over N; M = one 16-row mma block.
// __syncthreads() between levels orders this CTA's global writes/reads.
// ---------------------------------------------------------------------------
__global__ void __launch_bounds__(256, 4) k_finish(
    const float* __restrict__ b1, const float* __restrict__ b2,
    const float* __restrict__ lnw, const float* __restrict__ lnb,
    const int* __restrict__ lim)
{
    __shared__ __align__(16) unsigned char Xhi[16 * PITCHB];   // 8448 B
    __shared__ __align__(16) unsigned char Xlo[16 * PITCHB];

    int item = blockIdx.x;
    bool is64 = (lim[1] == 0);
    int L = get_limit(lim, is64, item + 1) - get_limit(lim, is64, item);
    int s = 0, l = L;
    #pragma unroll
    for (int t = 0; t < 4; t++) { int pr = l >> 1; s += 2 * pr; l = (l + 1) >> 1; }
    if (l < 2) return;
    int rowb = item * RPI;

    uint32_t XhiA = smem_u32(Xhi);
    uint32_t XloA = smem_u32(Xlo);
    int tid = threadIdx.x;
    int warp = tid >> 5, lane = tid & 31;
    int lrow = lane & 15;
    int lcol = (lane >> 4) << 3;

    #pragma unroll 1
    for (int lev = 0; lev < 4 && l >= 2; lev++) {
        int pairs = l >> 1;    // 1..8

        // Gather: pair r = tree rows (rowb+s+2r, +1) = 32 contiguous uint4
        {
            const uint4* sh = (const uint4*)g_bufh;
            const uint4* sl = (const uint4*)g_bufl;
            int tot = pairs * 32;
            for (int f = tid; f < tot; f += 256) {
                int r = f >> 5, q = f & 31;
                long gsrc = (long)(rowb + s + 2 * r) * 16 + q;
                *(uint4*)(Xhi + r * PITCHB + q * 16) = sh[gsrc];
                *(uint4*)(Xlo + r * PITCHB + q * 16) = sl[gsrc];
            }
        }
        __syncthreads();

        // GEMM1: M=16 block (rows >= pairs garbage), warp tile 16 x 32
        float acc[4][4];
        #pragma unroll
        for (int nt = 0; nt < 4; nt++)
            #pragma unroll
            for (int e = 0; e < 4; e++) acc[nt][e] = 0.f;
        #pragma unroll 1
        for (int term = 0; term < 3; term++) {
            uint32_t Aa = (term == 2) ? XloA : XhiA;
            const uint2* __restrict__ B = (term == 1) ? g_W1lo : g_W1hi;
            #pragma unroll 4
            for (int ks = 0; ks < 16; ks++) {
                uint32_t a[4];
                ldm4(a, Aa + (uint32_t)lrow * PITCHB + (uint32_t)(ks * 16 + lcol) * 2);
                #pragma unroll
                for (int nt = 0; nt < 4; nt++) {
                    uint2 b = B[(ks * 32 + warp * 4 + nt) * 32 + lane];
                    mma16816(acc[nt], a, b);
                }
            }
        }
        __syncthreads();

        // Epilogue1 -> H images
        {
            int row = lane >> 2;
            #pragma unroll
            for (int nt = 0; nt < 4; nt++) {
                int col = (warp * 4 + nt) * 8 + (lane & 3) * 2;
                float v0 = fmaxf(acc[nt][0] + b1[col], 0.f);
                float v1 = fmaxf(acc[nt][1] + b1[col + 1], 0.f);
                float v2 = fmaxf(acc[nt][2] + b1[col], 0.f);
                float v3 = fmaxf(acc[nt][3] + b1[col + 1], 0.f);
                unsigned short h0, l0_, h1, l1_, h2, l2_, h3, l3_;
                split2(v0, h0, l0_); split2(v1, h1, l1_);
                split2(v2, h2, l2_); split2(v3, h3, l3_);
                *(uint32_t*)(Xhi + row * PITCHB + col * 2)       = pk(h0, h1);
                *(uint32_t*)(Xlo + row * PITCHB + col * 2)       = pk(l0_, l1_);
                *(uint32_t*)(Xhi + (row + 8) * PITCHB + col * 2) = pk(h2, h3);
                *(uint32_t*)(Xlo + (row + 8) * PITCHB + col * 2) = pk(l2_, l3_);
            }
        }
        __syncthreads();

        // GEMM2: warp tile 16 x 16
        float acc2[2][4];
        #pragma unroll
        for (int nt = 0; nt < 2; nt++)
            #pragma unroll
            for (int e = 0; e < 4; e++) acc2[nt][e] = 0.f;
        #pragma unroll 1
        for (int term = 0; term < 3; term++) {
            uint32_t Aa = (term == 2) ? XloA : XhiA;
            const uint2* __restrict__ B = (term == 1) ? g_W2lo : g_W2hi;
            #pragma unroll 4
            for (int ks = 0; ks < 16; ks++) {
                uint32_t a[4];
                ldm4(a, Aa + (uint32_t)lrow * PITCHB + (uint32_t)(ks * 16 + lcol) * 2);
                #pragma unroll
                for (int nt = 0; nt < 2; nt++) {
                    uint2 b = B[(ks * 16 + warp * 2 + nt) * 32 + lane];
                    mma16816(acc2[nt], a, b);
                }
            }
        }
        __syncthreads();   // done reading H before Ys overlays Xhi

        // Epilogue2a: Y -> f32 smem [16][132] (overlays Xhi: 8448 B exact)
        float* Ys = (float*)Xhi;
        {
            int row = lane >> 2;
            #pragma unroll
            for (int nt = 0; nt < 2; nt++) {
                int col = (warp * 2 + nt) * 8 + (lane & 3) * 2;
                *(float2*)(Ys + row * 132 + col) =
                    make_float2(acc2[nt][0] + b2[col], acc2[nt][1] + b2[col + 1]);
                *(float2*)(Ys + (row + 8) * 132 + col) =
                    make_float2(acc2[nt][2] + b2[col], acc2[nt][3] + b2[col + 1]);
            }
        }
        __syncthreads();

        // Epilogue2b: LN rows 0..pairs-1 (warp w -> row w), store hi/lo
        if (warp < pairs) {
            int row = warp;
            long d = rowb + s + l + row;
            float4 y = *(const float4*)(Ys + row * 132 + lane * 4);
            float sum = y.x + y.y + y.z + y.w;
            float sq  = y.x * y.x + y.y * y.y + y.z * y.z + y.w * y.w;
            #pragma unroll
            for (int o = 16; o > 0; o >>= 1) {
                sum += __shfl_xor_sync(0xFFFFFFFFu, sum, o);
                sq  += __shfl_xor_sync(0xFFFFFFFFu, sq, o);
            }
            float mu  = sum * (1.f / 128.f);
            float var = sq * (1.f / 128.f) - mu * mu;
            float rs  = rsqrtf(var + 1e-5f);
            float4 wv = ((const float4*)lnw)[lane];
            float4 bv = ((const float4*)lnb)[lane];
            float4 o;
            o.x = (y.x - mu) * rs * wv.x + bv.x;
            o.y = (y.y - mu) * rs * wv.y + bv.y;
            o.z = (y.z - mu) * rs * wv.z + bv.z;
            o.w = (y.w - mu) * rs * wv.w + bv.w;
            unsigned short h0, l0_, h1, l1_, h2, l2_, h3, l3_;
            split2(o.x, h0, l0_); split2(o.y, h1, l1_);
            split2(o.z, h2, l2_); split2(o.w, h3, l3_);
            ((uint2*)g_bufh)[d * 32 + lane] = make_uint2(pk(h0, h1), pk(h2, h3));
            ((uint2*)g_bufl)[d * 32 + lane] = make_uint2(pk(l0_, l1_), pk(l2_, l3_));
        }
        s += 2 * pairs;
        l = (l + 1) >> 1;
        __syncthreads();
    }
}

// ---------------------------------------------------------------------------
__global__ void k_gather(float* __restrict__ out, const int* __restrict__ lim) {
    int item = blockIdx.x;
    bool is64 = (lim[1] == 0);
    int L = get_limit(lim, is64, item + 1) - get_limit(lim, is64, item);
    long idx = ((long)item * RPI + (2 * L - 2)) * DIM + threadIdx.x;
    out[item * DIM + threadIdx.x] =
        __bfloat162float(g_bufh[idx]) + __bfloat162float(g_bufl[idx]);
}

// ---------------------------------------------------------------------------
extern "C" void kernel_launch(void* const* d_in, const int* in_sizes, int n_in,
                              void* d_out, int out_size) {
    const float* args = (const float*)d_in[0];
    const int*   lim  = (const int*)d_in[1];
    const float* W1   = (const float*)d_in[2];
    const float* b1   = (const float*)d_in[3];
    const float* W2   = (const float*)d_in[4];
    const float* b2   = (const float*)d_in[5];
    const float* lnw  = (const float*)d_in[6];
    const float* lnb  = (const float*)d_in[7];
    float* out = (float*)d_out;
    (void)in_sizes; (void)n_in; (void)out_size;

    cudaFuncSetAttribute(k_level_mma, cudaFuncAttributeMaxDynamicSharedMemorySize, 2 * XBYTES);

    k_wprep<<<64, 256>>>(W1, W2);
    dim3 gsc(4, NITEMS);
    k_scatter<<<gsc, 256>>>(args, lim);
    k_scan<<<1, NITEMS>>>(lim);
    k_fill<<<NITEMS, 128>>>(lim);

    for (int k = 0; k < 4; k++) {
        int mp = NITEMS * (MAXM >> (k + 1));
        int ctas = (mp + TM - 1) / TM;
        k_level_mma<<<ctas, 256, 2 * XBYTES>>>(b1, b2, lnw, lnb, k);
    }
    k_finish<<<NITEMS, 256>>>(b1, b2, lnw, lnb, lim);

    k_gather<<<NITEMS, DIM>>>(out, lim);
}

// round 10
// speedup vs baseline: 2.0823x; 1.0627x over previous
#include <cuda_runtime.h>
#include <cuda_bf16.h>
#include <stdint.h>

#define NITEMS 512
#define MAXM   256
#define DIM    128
#define RPI    512
#define MAXPAIRS 131072
#define TM     64
#define PITCHB 528           // smem row pitch in bytes (264 bf16)
#define XBYTES 33792         // 64 * 528

__device__ __nv_bfloat16  g_bufh [(long)NITEMS * RPI * DIM];
__device__ __nv_bfloat16  g_bufl [(long)NITEMS * RPI * DIM];
// Weight images pre-packed in mma.m16n8k16 B-fragment order:
// [kstep][ntile][lane] -> uint2 (reg b0, reg b1)
__device__ uint2 g_W1hi[16 * 32 * 32];
__device__ uint2 g_W1lo[16 * 32 * 32];
__device__ uint2 g_W2hi[16 * 16 * 32];
__device__ uint2 g_W2lo[16 * 16 * 32];
__device__ int g_src[MAXPAIRS];
__device__ int g_dst[MAXPAIRS];
__device__ int g_off[4 * NITEMS];
__device__ int g_count[4];
__device__ int g_base[4];

__device__ __forceinline__ int get_limit(const int* lim, bool is64, int i) {
    return is64 ? lim[2 * i] : lim[i];
}
__device__ __forceinline__ void split2(float v, unsigned short& h, unsigned short& l) {
    __nv_bfloat16 hb = __float2bfloat16(v);
    __nv_bfloat16 lb = __float2bfloat16(v - __bfloat162float(hb));
    h = __bfloat16_as_ushort(hb); l = __bfloat16_as_ushort(lb);
}
__device__ __forceinline__ uint32_t pk(unsigned short a, unsigned short b) {
    return (uint32_t)a | ((uint32_t)b << 16);
}
__device__ __forceinline__ uint32_t smem_u32(const void* p) {
    uint32_t a;
    asm("{ .reg .u64 t; cvta.to.shared.u64 t, %1; cvt.u32.u64 %0, t; }" : "=r"(a) : "l"(p));
    return a;
}
__device__ __forceinline__ void ldm4(uint32_t* a, uint32_t addr) {
    asm volatile("ldmatrix.sync.aligned.m8n8.x4.shared.b16 {%0,%1,%2,%3}, [%4];"
                 : "=r"(a[0]), "=r"(a[1]), "=r"(a[2]), "=r"(a[3]) : "r"(addr));
}
__device__ __forceinline__ void mma16816(float* c, const uint32_t* a, uint2 b) {
    asm volatile(
        "mma.sync.aligned.m16n8k16.row.col.f32.bf16.bf16.f32 "
        "{%0,%1,%2,%3}, {%4,%5,%6,%7}, {%8,%9}, {%0,%1,%2,%3};"
        : "+f"(c[0]), "+f"(c[1]), "+f"(c[2]), "+f"(c[3])
        : "r"(a[0]), "r"(a[1]), "r"(a[2]), "r"(a[3]), "r"(b.x), "r"(b.y));
}

// ---------------------------------------------------------------------------
// Scatter (vectorized): args rows -> tree buffer hi/lo. float4 in, uint2 out.
// ---------------------------------------------------------------------------
__global__ void k_scatter(const float* __restrict__ args, const int* __restrict__ lim) {
    int item = blockIdx.y;
    bool is64 = (lim[1] == 0);
    int start = get_limit(lim, is64, item);
    int L     = get_limit(lim, is64, item + 1) - start;
    int r0 = blockIdx.x * 64;
    int nrows = min(64, L - r0);
    if (nrows <= 0) return;
    const float4* src = (const float4*)(args + (long)(start + r0) * DIM);
    uint2* dh = (uint2*)(g_bufh + ((long)item * RPI + r0) * DIM);
    uint2* dl = (uint2*)(g_bufl + ((long)item * RPI + r0) * DIM);
    int total = nrows * (DIM / 4);
    for (int i = threadIdx.x; i < total; i += blockDim.x) {
        float4 x = src[i];
        unsigned short h0, l0, h1, l1, h2, l2, h3, l3;
        split2(x.x, h0, l0); split2(x.y, h1, l1);
        split2(x.z, h2, l2); split2(x.w, h3, l3);
        dh[i] = make_uint2(pk(h0, h1), pk(h2, h3));
        dl[i] = make_uint2(pk(l0, l1), pk(l2, l3));
    }
}

// ---------------------------------------------------------------------------
// Scan: per-level totals + per-item exclusive offsets (levels 0..3).
// ---------------------------------------------------------------------------
__global__ void k_scan(const int* __restrict__ lim) {
    __shared__ int sc[NITEMS];
    int i = threadIdx.x;
    bool is64 = (lim[1] == 0);
    int L = get_limit(lim, is64, i + 1) - get_limit(lim, is64, i);
    int l = L, base = 0;
    for (int k = 0; k < 4; k++) {
        int pr = l >> 1;
        sc[i] = pr;
        __syncthreads();
        for (int off = 1; off < NITEMS; off <<= 1) {
            int v = sc[i];
            int w = (i >= off) ? sc[i - off] : 0;
            __syncthreads();
            sc[i] = v + w;
            __syncthreads();
        }
        g_off[k * NITEMS + i] = sc[i] - pr;
        if (i == 0) { g_count[k] = sc[NITEMS - 1]; g_base[k] = base; }
        base += sc[NITEMS - 1];
        l = (l + 1) >> 1;
        __syncthreads();
    }
}

// ---------------------------------------------------------------------------
// Fill pair lists (levels 0..3) + weight prep fused (blocks 0..63 pack W).
// grid 512, 256 threads.
// ---------------------------------------------------------------------------
__global__ void k_fillw(const int* __restrict__ lim,
                        const float* __restrict__ W1, const float* __restrict__ W2) {
    // ---- weight packing on blocks 0..63 ----
    if (blockIdx.x < 64) {
        int g = blockIdx.x * 256 + threadIdx.x;        // [0, 16384)
        int kstep = g >> 10, ntile = (g >> 5) & 31, lane = g & 31;
        int kb = kstep * 16 + (lane & 3) * 2;
        {
            int n = ntile * 8 + (lane >> 2);
            unsigned short h00, l00, h01, l01, h10, l10, h11, l11;
            split2(W1[kb * 256 + n],       h00, l00);
            split2(W1[(kb + 1) * 256 + n], h01, l01);
            split2(W1[(kb + 8) * 256 + n], h10, l10);
            split2(W1[(kb + 9) * 256 + n], h11, l11);
            int idx = (kstep * 32 + ntile) * 32 + lane;
            g_W1hi[idx] = make_uint2(pk(h00, h01), pk(h10, h11));
            g_W1lo[idx] = make_uint2(pk(l00, l01), pk(l10, l11));
        }
        if (ntile < 16) {
            int n = ntile * 8 + (lane >> 2);
            unsigned short h00, l00, h01, l01, h10, l10, h11, l11;
            split2(W2[kb * 128 + n],       h00, l00);
            split2(W2[(kb + 1) * 128 + n], h01, l01);
            split2(W2[(kb + 8) * 128 + n], h10, l10);
            split2(W2[(kb + 9) * 128 + n], h11, l11);
            int idx = (kstep * 16 + ntile) * 32 + lane;
            g_W2hi[idx] = make_uint2(pk(h00, h01), pk(h10, h11));
            g_W2lo[idx] = make_uint2(pk(l00, l01), pk(l10, l11));
        }
    }
    // ---- pair list fill (all 512 blocks; one item each) ----
    int item = blockIdx.x;
    bool is64 = (lim[1] == 0);
    int L = get_limit(lim, is64, item + 1) - get_limit(lim, is64, item);
    int s = 0, l = L;
    int rowb = item * RPI;
    for (int k = 0; k < 4; k++) {
        int pr = l >> 1;
        int e = g_base[k] + g_off[k * NITEMS + item];
        for (int p = threadIdx.x; p < pr; p += blockDim.x) {
            g_src[e + p] = rowb + s + 2 * p;
            g_dst[e + p] = rowb + s + l + p;
        }
        s += 2 * pr;
        l = (l + 1) >> 1;
    }
}

// ---------------------------------------------------------------------------
// Batched level kernel (levels 0..3): 64 pairs/CTA, 8 warps (2 M x 4 N).
// ---------------------------------------------------------------------------
extern __shared__ __align__(16) unsigned char smraw[];

__global__ void __launch_bounds__(256, 2) k_level_mma(
    const float* __restrict__ b1, const float* __restrict__ b2,
    const float* __restrict__ lnw, const float* __restrict__ lnb, int level)
{
    int cnt = g_count[level], base = g_base[level];
    int j0 = blockIdx.x * TM;
    if (j0 >= cnt) return;
    int np = min(TM, cnt - j0);

    unsigned char* Xhi = smraw;
    unsigned char* Xlo = smraw + XBYTES;
    uint32_t XhiA = smem_u32(Xhi);
    uint32_t XloA = XhiA + XBYTES;

    int tid = threadIdx.x;
    int warp = tid >> 5, lane = tid & 31;
    int warp_m = warp & 1, warp_n = warp >> 1;

    {
        const uint4* sh = (const uint4*)g_bufh;
        const uint4* sl = (const uint4*)g_bufl;
        #pragma unroll
        for (int it = 0; it < 8; it++) {
            int f = it * 256 + tid;
            int r = f >> 5, q = f & 31;
            int rc = min(r, np - 1);
            int sr = g_src[base + j0 + rc];
            *(uint4*)(Xhi + r * PITCHB + q * 16) = sh[(long)sr * 16 + q];
            *(uint4*)(Xlo + r * PITCHB + q * 16) = sl[(long)sr * 16 + q];
        }
    }
    __syncthreads();

    int lrow = lane & 15;
    int lcol = (lane >> 4) << 3;

    // ---- GEMM1 ----
    float acc[2][8][4];
    #pragma unroll
    for (int rb = 0; rb < 2; rb++)
        #pragma unroll
        for (int nt = 0; nt < 8; nt++)
            #pragma unroll
            for (int e = 0; e < 4; e++) acc[rb][nt][e] = 0.f;

    #pragma unroll 1
    for (int term = 0; term < 3; term++) {
        uint32_t Aa = (term == 2) ? XloA : XhiA;
        const uint2* __restrict__ B = (term == 1) ? g_W1lo : g_W1hi;
        #pragma unroll 4
        for (int ks = 0; ks < 16; ks++) {
            uint32_t a0[4], a1[4];
            uint32_t col2 = (uint32_t)(ks * 16 + lcol) * 2;
            ldm4(a0, Aa + (uint32_t)(warp_m * 32 + lrow) * PITCHB + col2);
            ldm4(a1, Aa + (uint32_t)(warp_m * 32 + 16 + lrow) * PITCHB + col2);
            #pragma unroll
            for (int nt = 0; nt < 8; nt++) {
                uint2 b = B[(ks * 32 + warp_n * 8 + nt) * 32 + lane];
                mma16816(acc[0][nt], a0, b);
                mma16816(acc[1][nt], a1, b);
            }
        }
    }
    __syncthreads();

    // ---- Epilogue1: H = relu(acc + b1) -> X images ----
    #pragma unroll
    for (int rb = 0; rb < 2; rb++) {
        int row = warp_m * 32 + rb * 16 + (lane >> 2);
        #pragma unroll
        for (int nt = 0; nt < 8; nt++) {
            int col = (warp_n * 8 + nt) * 8 + (lane & 3) * 2;
            float v0 = fmaxf(acc[rb][nt][0] + b1[col], 0.f);
            float v1 = fmaxf(acc[rb][nt][1] + b1[col + 1], 0.f);
            float v2 = fmaxf(acc[rb][nt][2] + b1[col], 0.f);
            float v3 = fmaxf(acc[rb][nt][3] + b1[col + 1], 0.f);
            unsigned short h0, l0, h1, l1, h2, l2, h3, l3;
            split2(v0, h0, l0); split2(v1, h1, l1);
            split2(v2, h2, l2); split2(v3, h3, l3);
            *(uint32_t*)(Xhi + row * PITCHB + col * 2)       = pk(h0, h1);
            *(uint32_t*)(Xlo + row * PITCHB + col * 2)       = pk(l0, l1);
            *(uint32_t*)(Xhi + (row + 8) * PITCHB + col * 2) = pk(h2, h3);
            *(uint32_t*)(Xlo + (row + 8) * PITCHB + col * 2) = pk(l2, l3);
        }
    }
    __syncthreads();

    // ---- GEMM2 ----
    float acc2[2][4][4];
    #pragma unroll
    for (int rb = 0; rb < 2; rb++)
        #pragma unroll
        for (int nt = 0; nt < 4; nt++)
            #pragma unroll
            for (int e = 0; e < 4; e++) acc2[rb][nt][e] = 0.f;

    #pragma unroll 1
    for (int term = 0; term < 3; term++) {
        uint32_t Aa = (term == 2) ? XloA : XhiA;
        const uint2* __restrict__ B = (term == 1) ? g_W2lo : g_W2hi;
        #pragma unroll 4
        for (int ks = 0; ks < 16; ks++) {
            uint32_t a0[4], a1[4];
            uint32_t col2 = (uint32_t)(ks * 16 + lcol) * 2;
            ldm4(a0, Aa + (uint32_t)(warp_m * 32 + lrow) * PITCHB + col2);
            ldm4(a1, Aa + (uint32_t)(warp_m * 32 + 16 + lrow) * PITCHB + col2);
            #pragma unroll
            for (int nt = 0; nt < 4; nt++) {
                uint2 b = B[(ks * 16 + warp_n * 4 + nt) * 32 + lane];
                mma16816(acc2[0][nt], a0, b);
                mma16816(acc2[1][nt], a1, b);
            }
        }
    }
    __syncthreads();

    // ---- Epilogue2a: Y -> f32 smem [64][132] ----
    float* Ys = (float*)Xhi;
    #pragma unroll
    for (int rb = 0; rb < 2; rb++) {
        int row = warp_m * 32 + rb * 16 + (lane >> 2);
        #pragma unroll
        for (int nt = 0; nt < 4; nt++) {
            int col = (warp_n * 4 + nt) * 8 + (lane & 3) * 2;
            *(float2*)(Ys + row * 132 + col) =
                make_float2(acc2[rb][nt][0] + b2[col], acc2[rb][nt][1] + b2[col + 1]);
            *(float2*)(Ys + (row + 8) * 132 + col) =
                make_float2(acc2[rb][nt][2] + b2[col], acc2[rb][nt][3] + b2[col + 1]);
        }
    }
    __syncthreads();

    // ---- Epilogue2b: LayerNorm + store hi/lo ----
    #pragma unroll
    for (int rr = 0; rr < 8; rr++) {
        int row = warp * 8 + rr;
        int d = (row < np) ? g_dst[base + j0 + row] : -1;
        float4 y = *(const float4*)(Ys + row * 132 + lane * 4);
        float sum = y.x + y.y + y.z + y.w;
        float sq  = y.x * y.x + y.y * y.y + y.z * y.z + y.w * y.w;
        #pragma unroll
        for (int o = 16; o > 0; o >>= 1) {
            sum += __shfl_xor_sync(0xFFFFFFFFu, sum, o);
            sq  += __shfl_xor_sync(0xFFFFFFFFu, sq, o);
        }
        float mu  = sum * (1.f / 128.f);
        float var = sq * (1.f / 128.f) - mu * mu;
        float rs  = rsqrtf(var + 1e-5f);
        float4 wv = ((const float4*)lnw)[lane];
        float4 bv = ((const float4*)lnb)[lane];
        float4 o;
        o.x = (y.x - mu) * rs * wv.x + bv.x;
        o.y = (y.y - mu) * rs * wv.y + bv.y;
        o.z = (y.z - mu) * rs * wv.z + bv.z;
        o.w = (y.w - mu) * rs * wv.w + bv.w;
        if (d >= 0) {
            unsigned short h0, l0, h1, l1, h2, l2, h3, l3;
            split2(o.x, h0, l0); split2(o.y, h1, l1);
            split2(o.z, h2, l2); split2(o.w, h3, l3);
            ((uint2*)g_bufh)[(long)d * 32 + lane] = make_uint2(pk(h0, h1), pk(h2, h3));
            ((uint2*)g_bufl)[(long)d * 32 + lane] = make_uint2(pk(l0, l1), pk(l2, l3));
        }
    }
}

// ---------------------------------------------------------------------------
// Finisher: one CTA per item handles tree levels 4..7 and writes the output
// row (gather fused). 8 warps spread over N; M = one 16-row mma block.
// ---------------------------------------------------------------------------
__global__ void __launch_bounds__(256, 4) k_finish(
    const float* __restrict__ b1, const float* __restrict__ b2,
    const float* __restrict__ lnw, const float* __restrict__ lnb,
    const int* __restrict__ lim, float* __restrict__ out)
{
    __shared__ __align__(16) unsigned char Xhi[16 * PITCHB];   // 8448 B
    __shared__ __align__(16) unsigned char Xlo[16 * PITCHB];

    int item = blockIdx.x;
    bool is64 = (lim[1] == 0);
    int L = get_limit(lim, is64, item + 1) - get_limit(lim, is64, item);
    int s = 0, l = L;
    #pragma unroll
    for (int t = 0; t < 4; t++) { int pr = l >> 1; s += 2 * pr; l = (l + 1) >> 1; }
    int rowb = item * RPI;

    uint32_t XhiA = smem_u32(Xhi);
    uint32_t XloA = smem_u32(Xlo);
    int tid = threadIdx.x;
    int warp = tid >> 5, lane = tid & 31;
    int lrow = lane & 15;
    int lcol = (lane >> 4) << 3;

    #pragma unroll 1
    for (int lev = 0; lev < 4 && l >= 2; lev++) {
        int pairs = l >> 1;    // 1..8

        {
            const uint4* sh = (const uint4*)g_bufh;
            const uint4* sl = (const uint4*)g_bufl;
            int tot = pairs * 32;
            for (int f = tid; f < tot; f += 256) {
                int r = f >> 5, q = f & 31;
                long gsrc = (long)(rowb + s + 2 * r) * 16 + q;
                *(uint4*)(Xhi + r * PITCHB + q * 16) = sh[gsrc];
                *(uint4*)(Xlo + r * PITCHB + q * 16) = sl[gsrc];
            }
        }
        __syncthreads();

        // GEMM1: warp tile 16 x 32
        float acc[4][4];
        #pragma unroll
        for (int nt = 0; nt < 4; nt++)
            #pragma unroll
            for (int e = 0; e < 4; e++) acc[nt][e] = 0.f;
        #pragma unroll 1
        for (int term = 0; term < 3; term++) {
            uint32_t Aa = (term == 2) ? XloA : XhiA;
            const uint2* __restrict__ B = (term == 1) ? g_W1lo : g_W1hi;
            #pragma unroll 4
            for (int ks = 0; ks < 16; ks++) {
                uint32_t a[4];
                ldm4(a, Aa + (uint32_t)lrow * PITCHB + (uint32_t)(ks * 16 + lcol) * 2);
                #pragma unroll
                for (int nt = 0; nt < 4; nt++) {
                    uint2 b = B[(ks * 32 + warp * 4 + nt) * 32 + lane];
                    mma16816(acc[nt], a, b);
                }
            }
        }
        __syncthreads();

        {
            int row = lane >> 2;
            #pragma unroll
            for (int nt = 0; nt < 4; nt++) {
                int col = (warp * 4 + nt) * 8 + (lane & 3) * 2;
                float v0 = fmaxf(acc[nt][0] + b1[col], 0.f);
                float v1 = fmaxf(acc[nt][1] + b1[col + 1], 0.f);
                float v2 = fmaxf(acc[nt][2] + b1[col], 0.f);
                float v3 = fmaxf(acc[nt][3] + b1[col + 1], 0.f);
                unsigned short h0, l0_, h1, l1_, h2, l2_, h3, l3_;
                split2(v0, h0, l0_); split2(v1, h1, l1_);
                split2(v2, h2, l2_); split2(v3, h3, l3_);
                *(uint32_t*)(Xhi + row * PITCHB + col * 2)       = pk(h0, h1);
                *(uint32_t*)(Xlo + row * PITCHB + col * 2)       = pk(l0_, l1_);
                *(uint32_t*)(Xhi + (row + 8) * PITCHB + col * 2) = pk(h2, h3);
                *(uint32_t*)(Xlo + (row + 8) * PITCHB + col * 2) = pk(l2_, l3_);
            }
        }
        __syncthreads();

        // GEMM2: warp tile 16 x 16
        float acc2[2][4];
        #pragma unroll
        for (int nt = 0; nt < 2; nt++)
            #pragma unroll
            for (int e = 0; e < 4; e++) acc2[nt][e] = 0.f;
        #pragma unroll 1
        for (int term = 0; term < 3; term++) {
            uint32_t Aa = (term == 2) ? XloA : XhiA;
            const uint2* __restrict__ B = (term == 1) ? g_W2lo : g_W2hi;
            #pragma unroll 4
            for (int ks = 0; ks < 16; ks++) {
                uint32_t a[4];
                ldm4(a, Aa + (uint32_t)lrow * PITCHB + (uint32_t)(ks * 16 + lcol) * 2);
                #pragma unroll
                for (int nt = 0; nt < 2; nt++) {
                    uint2 b = B[(ks * 16 + warp * 2 + nt) * 32 + lane];
                    mma16816(acc2[nt], a, b);
                }
            }
        }
        __syncthreads();

        float* Ys = (float*)Xhi;
        {
            int row = lane >> 2;
            #pragma unroll
            for (int nt = 0; nt < 2; nt++) {
                int col = (warp * 2 + nt) * 8 + (lane & 3) * 2;
                *(float2*)(Ys + row * 132 + col) =
                    make_float2(acc2[nt][0] + b2[col], acc2[nt][1] + b2[col + 1]);
                *(float2*)(Ys + (row + 8) * 132 + col) =
                    make_float2(acc2[nt][2] + b2[col], acc2[nt][3] + b2[col + 1]);
            }
        }
        __syncthreads();

        if (warp < pairs) {
            int row = warp;
            long d = rowb + s + l + row;
            float4 y = *(const float4*)(Ys + row * 132 + lane * 4);
            float sum = y.x + y.y + y.z + y.w;
            float sq  = y.x * y.x + y.y * y.y + y.z * y.z + y.w * y.w;
            #pragma unroll
            for (int o = 16; o > 0; o >>= 1) {
                sum += __shfl_xor_sync(0xFFFFFFFFu, sum, o);
                sq  += __shfl_xor_sync(0xFFFFFFFFu, sq, o);
            }
            float mu  = sum * (1.f / 128.f);
            float var = sq * (1.f / 128.f) - mu * mu;
            float rs  = rsqrtf(var + 1e-5f);
            float4 wv = ((const float4*)lnw)[lane];
            float4 bv = ((const float4*)lnb)[lane];
            float4 o;
            o.x = (y.x - mu) * rs * wv.x + bv.x;
            o.y = (y.y - mu) * rs * wv.y + bv.y;
            o.z = (y.z - mu) * rs * wv.z + bv.z;
            o.w = (y.w - mu) * rs * wv.w + bv.w;
            unsigned short h0, l0_, h1, l1_, h2, l2_, h3, l3_;
            split2(o.x, h0, l0_); split2(o.y, h1, l1_);
            split2(o.z, h2, l2_); split2(o.w, h3, l3_);
            ((uint2*)g_bufh)[d * 32 + lane] = make_uint2(pk(h0, h1), pk(h2, h3));
            ((uint2*)g_bufl)[d * 32 + lane] = make_uint2(pk(l0_, l1_), pk(l2_, l3_));
        }
        s += 2 * pairs;
        l = (l + 1) >> 1;
        __syncthreads();
    }

    // ---- Gather fused: out[item] = hi + lo of root row (2L-2) ----
    if (tid < DIM) {
        long idx = ((long)rowb + (2 * L - 2)) * DIM + tid;
        out[item * DIM + tid] =
            __bfloat162float(g_bufh[idx]) + __bfloat162float(g_bufl[idx]);
    }
}

// ---------------------------------------------------------------------------
extern "C" void kernel_launch(void* const* d_in, const int* in_sizes, int n_in,
                              void* d_out, int out_size) {
    const float* args = (const float*)d_in[0];
    const int*   lim  = (const int*)d_in[1];
    const float* W1   = (const float*)d_in[2];
    const float* b1   = (const float*)d_in[3];
    const float* W2   = (const float*)d_in[4];
    const float* b2   = (const float*)d_in[5];
    const float* lnw  = (const float*)d_in[6];
    const float* lnb  = (const float*)d_in[7];
    float* out = (float*)d_out;
    (void)in_sizes; (void)n_in; (void)out_size;

    cudaFuncSetAttribute(k_level_mma, cudaFuncAttributeMaxDynamicSharedMemorySize, 2 * XBYTES);

    dim3 gsc(4, NITEMS);
    k_scatter<<<gsc, 256>>>(args, lim);            // launch 1
    k_scan<<<1, NITEMS>>>(lim);                    // launch 2
    k_fillw<<<NITEMS, 256>>>(lim, W1, W2);         // launch 3 (fill + weight prep)

    for (int k = 0; k < 4; k++) {                  // launches 4..7 (level0 = #4 -> ncu)
        int mp = NITEMS * (MAXM >> (k + 1));
        int ctas = (mp + TM - 1) / TM;
        k_level_mma<<<ctas, 256, 2 * XBYTES>>>(b1, b2, lnw, lnb, k);
    }
    k_finish<<<NITEMS, 256>>>(b1, b2, lnw, lnb, lim, out);   // launch 8 (gather fused)
}

// round 11
// speedup vs baseline: 2.4493x; 1.1763x over previous
#include <cuda_runtime.h>
#include <cuda_bf16.h>
#include <stdint.h>

#define NITEMS 512
#define MAXM   256
#define DIM    128
#define RPI    512
#define MAXPAIRS 131072
#define TM     64
#define PITCHB 528           // smem row pitch in bytes (264 bf16)
#define XBYTES 33792         // 64 * 528

__device__ __nv_bfloat16  g_bufh [(long)NITEMS * RPI * DIM];
__device__ __nv_bfloat16  g_bufl [(long)NITEMS * RPI * DIM];
// Weight images pre-packed in mma.m16n8k16 B-fragment order:
// [kstep][ntile][lane] -> uint2 (reg b0, reg b1)
__device__ uint2 g_W1hi[16 * 32 * 32];
__device__ uint2 g_W1lo[16 * 32 * 32];
__device__ uint2 g_W2hi[16 * 16 * 32];
__device__ uint2 g_W2lo[16 * 16 * 32];
__device__ int g_src[MAXPAIRS];
__device__ int g_dst[MAXPAIRS];
__device__ int g_off[4 * NITEMS];
__device__ int g_count[4];
__device__ int g_base[4];

__device__ __forceinline__ int get_limit(const int* lim, bool is64, int i) {
    return is64 ? lim[2 * i] : lim[i];
}
__device__ __forceinline__ void split2(float v, unsigned short& h, unsigned short& l) {
    __nv_bfloat16 hb = __float2bfloat16(v);
    __nv_bfloat16 lb = __float2bfloat16(v - __bfloat162float(hb));
    h = __bfloat16_as_ushort(hb); l = __bfloat16_as_ushort(lb);
}
__device__ __forceinline__ uint32_t pk(unsigned short a, unsigned short b) {
    return (uint32_t)a | ((uint32_t)b << 16);
}
__device__ __forceinline__ uint32_t smem_u32(const void* p) {
    uint32_t a;
    asm("{ .reg .u64 t; cvta.to.shared.u64 t, %1; cvt.u32.u64 %0, t; }" : "=r"(a) : "l"(p));
    return a;
}
__device__ __forceinline__ void ldm4(uint32_t* a, uint32_t addr) {
    asm volatile("ldmatrix.sync.aligned.m8n8.x4.shared.b16 {%0,%1,%2,%3}, [%4];"
                 : "=r"(a[0]), "=r"(a[1]), "=r"(a[2]), "=r"(a[3]) : "r"(addr));
}
__device__ __forceinline__ void mma16816(float* c, const uint32_t* a, uint2 b) {
    asm volatile(
        "mma.sync.aligned.m16n8k16.row.col.f32.bf16.bf16.f32 "
        "{%0,%1,%2,%3}, {%4,%5,%6,%7}, {%8,%9}, {%0,%1,%2,%3};"
        : "+f"(c[0]), "+f"(c[1]), "+f"(c[2]), "+f"(c[3])
        : "r"(a[0]), "r"(a[1]), "r"(a[2]), "r"(a[3]), "r"(b.x), "r"(b.y));
}

// ---------------------------------------------------------------------------
// Scatter (vectorized): args rows -> tree buffer hi/lo.
// ---------------------------------------------------------------------------
__global__ void k_scatter(const float* __restrict__ args, const int* __restrict__ lim) {
    int item = blockIdx.y;
    bool is64 = (lim[1] == 0);
    int start = get_limit(lim, is64, item);
    int L     = get_limit(lim, is64, item + 1) - start;
    int r0 = blockIdx.x * 64;
    int nrows = min(64, L - r0);
    if (nrows <= 0) return;
    const float4* src = (const float4*)(args + (long)(start + r0) * DIM);
    uint2* dh = (uint2*)(g_bufh + ((long)item * RPI + r0) * DIM);
    uint2* dl = (uint2*)(g_bufl + ((long)item * RPI + r0) * DIM);
    int total = nrows * (DIM / 4);
    for (int i = threadIdx.x; i < total; i += blockDim.x) {
        float4 x = src[i];
        unsigned short h0, l0, h1, l1, h2, l2, h3, l3;
        split2(x.x, h0, l0); split2(x.y, h1, l1);
        split2(x.z, h2, l2); split2(x.w, h3, l3);
        dh[i] = make_uint2(pk(h0, h1), pk(h2, h3));
        dl[i] = make_uint2(pk(l0, l1), pk(l2, l3));
    }
}

// ---------------------------------------------------------------------------
__global__ void k_scan(const int* __restrict__ lim) {
    __shared__ int sc[NITEMS];
    int i = threadIdx.x;
    bool is64 = (lim[1] == 0);
    int L = get_limit(lim, is64, i + 1) - get_limit(lim, is64, i);
    int l = L, base = 0;
    for (int k = 0; k < 4; k++) {
        int pr = l >> 1;
        sc[i] = pr;
        __syncthreads();
        for (int off = 1; off < NITEMS; off <<= 1) {
            int v = sc[i];
            int w = (i >= off) ? sc[i - off] : 0;
            __syncthreads();
            sc[i] = v + w;
            __syncthreads();
        }
        g_off[k * NITEMS + i] = sc[i] - pr;
        if (i == 0) { g_count[k] = sc[NITEMS - 1]; g_base[k] = base; }
        base += sc[NITEMS - 1];
        l = (l + 1) >> 1;
        __syncthreads();
    }
}

// ---------------------------------------------------------------------------
// Fill pair lists (levels 0..3) + weight prep fused (blocks 0..63 pack W).
// ---------------------------------------------------------------------------
__global__ void k_fillw(const int* __restrict__ lim,
                        const float* __restrict__ W1, const float* __restrict__ W2) {
    if (blockIdx.x < 64) {
        int g = blockIdx.x * 256 + threadIdx.x;        // [0, 16384)
        int kstep = g >> 10, ntile = (g >> 5) & 31, lane = g & 31;
        int kb = kstep * 16 + (lane & 3) * 2;
        {
            int n = ntile * 8 + (lane >> 2);
            unsigned short h00, l00, h01, l01, h10, l10, h11, l11;
            split2(W1[kb * 256 + n],       h00, l00);
            split2(W1[(kb + 1) * 256 + n], h01, l01);
            split2(W1[(kb + 8) * 256 + n], h10, l10);
            split2(W1[(kb + 9) * 256 + n], h11, l11);
            int idx = (kstep * 32 + ntile) * 32 + lane;
            g_W1hi[idx] = make_uint2(pk(h00, h01), pk(h10, h11));
            g_W1lo[idx] = make_uint2(pk(l00, l01), pk(l10, l11));
        }
        if (ntile < 16) {
            int n = ntile * 8 + (lane >> 2);
            unsigned short h00, l00, h01, l01, h10, l10, h11, l11;
            split2(W2[kb * 128 + n],       h00, l00);
            split2(W2[(kb + 1) * 128 + n], h01, l01);
            split2(W2[(kb + 8) * 128 + n], h10, l10);
            split2(W2[(kb + 9) * 128 + n], h11, l11);
            int idx = (kstep * 16 + ntile) * 32 + lane;
            g_W2hi[idx] = make_uint2(pk(h00, h01), pk(h10, h11));
            g_W2lo[idx] = make_uint2(pk(l00, l01), pk(l10, l11));
        }
    }
    int item = blockIdx.x;
    bool is64 = (lim[1] == 0);
    int L = get_limit(lim, is64, item + 1) - get_limit(lim, is64, item);
    int s = 0, l = L;
    int rowb = item * RPI;
    for (int k = 0; k < 4; k++) {
        int pr = l >> 1;
        int e = g_base[k] + g_off[k * NITEMS + item];
        for (int p = threadIdx.x; p < pr; p += blockDim.x) {
            g_src[e + p] = rowb + s + 2 * p;
            g_dst[e + p] = rowb + s + l + p;
        }
        s += 2 * pr;
        l = (l + 1) >> 1;
    }
}

// ---------------------------------------------------------------------------
// Batched level kernel (levels 0..3): 64 pairs/CTA, 8 warps (2 M x 4 N).
// Fused 3-term mainloop: per ks load a_hi+a_lo once, per nt load b_hi+b_lo
// once; issue 6 mma (Ahi*Whi + Ahi*Wlo + Alo*Whi) per nt.
// ---------------------------------------------------------------------------
extern __shared__ __align__(16) unsigned char smraw[];

__global__ void __launch_bounds__(256, 2) k_level_mma(
    const float* __restrict__ b1, const float* __restrict__ b2,
    const float* __restrict__ lnw, const float* __restrict__ lnb, int level)
{
    int cnt = g_count[level], base = g_base[level];
    int j0 = blockIdx.x * TM;
    if (j0 >= cnt) return;
    int np = min(TM, cnt - j0);

    unsigned char* Xhi = smraw;
    unsigned char* Xlo = smraw + XBYTES;
    uint32_t XhiA = smem_u32(Xhi);
    uint32_t XloA = XhiA + XBYTES;

    int tid = threadIdx.x;
    int warp = tid >> 5, lane = tid & 31;
    int warp_m = warp & 1, warp_n = warp >> 1;

    {
        const uint4* sh = (const uint4*)g_bufh;
        const uint4* sl = (const uint4*)g_bufl;
        #pragma unroll
        for (int it = 0; it < 8; it++) {
            int f = it * 256 + tid;
            int r = f >> 5, q = f & 31;
            int rc = min(r, np - 1);
            int sr = g_src[base + j0 + rc];
            *(uint4*)(Xhi + r * PITCHB + q * 16) = sh[(long)sr * 16 + q];
            *(uint4*)(Xlo + r * PITCHB + q * 16) = sl[(long)sr * 16 + q];
        }
    }
    __syncthreads();

    int lrow = lane & 15;
    int lcol = (lane >> 4) << 3;
    uint32_t rowA0 = (uint32_t)(warp_m * 32 + lrow) * PITCHB;
    uint32_t rowA1 = (uint32_t)(warp_m * 32 + 16 + lrow) * PITCHB;

    // ---- GEMM1: fused 3-term ----
    float acc[2][8][4];
    #pragma unroll
    for (int rb = 0; rb < 2; rb++)
        #pragma unroll
        for (int nt = 0; nt < 8; nt++)
            #pragma unroll
            for (int e = 0; e < 4; e++) acc[rb][nt][e] = 0.f;

    #pragma unroll 2
    for (int ks = 0; ks < 16; ks++) {
        uint32_t col2 = (uint32_t)(ks * 16 + lcol) * 2;
        uint32_t ah0[4], ah1[4], al0[4], al1[4];
        ldm4(ah0, XhiA + rowA0 + col2);
        ldm4(ah1, XhiA + rowA1 + col2);
        ldm4(al0, XloA + rowA0 + col2);
        ldm4(al1, XloA + rowA1 + col2);
        #pragma unroll
        for (int nt = 0; nt < 8; nt++) {
            int bi = (ks * 32 + warp_n * 8 + nt) * 32 + lane;
            uint2 bh = g_W1hi[bi];
            uint2 bl = g_W1lo[bi];
            mma16816(acc[0][nt], ah0, bh);
            mma16816(acc[1][nt], ah1, bh);
            mma16816(acc[0][nt], ah0, bl);
            mma16816(acc[1][nt], ah1, bl);
            mma16816(acc[0][nt], al0, bh);
            mma16816(acc[1][nt], al1, bh);
        }
    }
    __syncthreads();

    // ---- Epilogue1: H = relu(acc + b1) -> X images ----
    #pragma unroll
    for (int rb = 0; rb < 2; rb++) {
        int row = warp_m * 32 + rb * 16 + (lane >> 2);
        #pragma unroll
        for (int nt = 0; nt < 8; nt++) {
            int col = (warp_n * 8 + nt) * 8 + (lane & 3) * 2;
            float v0 = fmaxf(acc[rb][nt][0] + b1[col], 0.f);
            float v1 = fmaxf(acc[rb][nt][1] + b1[col + 1], 0.f);
            float v2 = fmaxf(acc[rb][nt][2] + b1[col], 0.f);
            float v3 = fmaxf(acc[rb][nt][3] + b1[col + 1], 0.f);
            unsigned short h0, l0, h1, l1, h2, l2, h3, l3;
            split2(v0, h0, l0); split2(v1, h1, l1);
            split2(v2, h2, l2); split2(v3, h3, l3);
            *(uint32_t*)(Xhi + row * PITCHB + col * 2)       = pk(h0, h1);
            *(uint32_t*)(Xlo + row * PITCHB + col * 2)       = pk(l0, l1);
            *(uint32_t*)(Xhi + (row + 8) * PITCHB + col * 2) = pk(h2, h3);
            *(uint32_t*)(Xlo + (row + 8) * PITCHB + col * 2) = pk(l2, l3);
        }
    }
    __syncthreads();

    // ---- GEMM2: fused 3-term ----
    float acc2[2][4][4];
    #pragma unroll
    for (int rb = 0; rb < 2; rb++)
        #pragma unroll
        for (int nt = 0; nt < 4; nt++)
            #pragma unroll
            for (int e = 0; e < 4; e++) acc2[rb][nt][e] = 0.f;

    #pragma unroll 2
    for (int ks = 0; ks < 16; ks++) {
        uint32_t col2 = (uint32_t)(ks * 16 + lcol) * 2;
        uint32_t ah0[4], ah1[4], al0[4], al1[4];
        ldm4(ah0, XhiA + rowA0 + col2);
        ldm4(ah1, XhiA + rowA1 + col2);
        ldm4(al0, XloA + rowA0 + col2);
        ldm4(al1, XloA + rowA1 + col2);
        #pragma unroll
        for (int nt = 0; nt < 4; nt++) {
            int bi = (ks * 16 + warp_n * 4 + nt) * 32 + lane;
            uint2 bh = g_W2hi[bi];
            uint2 bl = g_W2lo[bi];
            mma16816(acc2[0][nt], ah0, bh);
            mma16816(acc2[1][nt], ah1, bh);
            mma16816(acc2[0][nt], ah0, bl);
            mma16816(acc2[1][nt], ah1, bl);
            mma16816(acc2[0][nt], al0, bh);
            mma16816(acc2[1][nt], al1, bh);
        }
    }
    __syncthreads();

    // ---- Epilogue2a: Y -> f32 smem [64][132] ----
    float* Ys = (float*)Xhi;
    #pragma unroll
    for (int rb = 0; rb < 2; rb++) {
        int row = warp_m * 32 + rb * 16 + (lane >> 2);
        #pragma unroll
        for (int nt = 0; nt < 4; nt++) {
            int col = (warp_n * 4 + nt) * 8 + (lane & 3) * 2;
            *(float2*)(Ys + row * 132 + col) =
                make_float2(acc2[rb][nt][0] + b2[col], acc2[rb][nt][1] + b2[col + 1]);
            *(float2*)(Ys + (row + 8) * 132 + col) =
                make_float2(acc2[rb][nt][2] + b2[col], acc2[rb][nt][3] + b2[col + 1]);
        }
    }
    __syncthreads();

    // ---- Epilogue2b: LayerNorm + store hi/lo ----
    #pragma unroll
    for (int rr = 0; rr < 8; rr++) {
        int row = warp * 8 + rr;
        int d = (row < np) ? g_dst[base + j0 + row] : -1;
        float4 y = *(const float4*)(Ys + row * 132 + lane * 4);
        float sum = y.x + y.y + y.z + y.w;
        float sq  = y.x * y.x + y.y * y.y + y.z * y.z + y.w * y.w;
        #pragma unroll
        for (int o = 16; o > 0; o >>= 1) {
            sum += __shfl_xor_sync(0xFFFFFFFFu, sum, o);
            sq  += __shfl_xor_sync(0xFFFFFFFFu, sq, o);
        }
        float mu  = sum * (1.f / 128.f);
        float var = sq * (1.f / 128.f) - mu * mu;
        float rs  = rsqrtf(var + 1e-5f);
        float4 wv = ((const float4*)lnw)[lane];
        float4 bv = ((const float4*)lnb)[lane];
        float4 o;
        o.x = (y.x - mu) * rs * wv.x + bv.x;
        o.y = (y.y - mu) * rs * wv.y + bv.y;
        o.z = (y.z - mu) * rs * wv.z + bv.z;
        o.w = (y.w - mu) * rs * wv.w + bv.w;
        if (d >= 0) {
            unsigned short h0, l0, h1, l1, h2, l2, h3, l3;
            split2(o.x, h0, l0); split2(o.y, h1, l1);
            split2(o.z, h2, l2); split2(o.w, h3, l3);
            ((uint2*)g_bufh)[(long)d * 32 + lane] = make_uint2(pk(h0, h1), pk(h2, h3));
            ((uint2*)g_bufl)[(long)d * 32 + lane] = make_uint2(pk(l0, l1), pk(l2, l3));
        }
    }
}

// ---------------------------------------------------------------------------
// Finisher: one CTA per item, levels 4..7 + fused gather. Fused 3-term loops.
// ---------------------------------------------------------------------------
__global__ void __launch_bounds__(256, 4) k_finish(
    const float* __restrict__ b1, const float* __restrict__ b2,
    const float* __restrict__ lnw, const float* __restrict__ lnb,
    const int* __restrict__ lim, float* __restrict__ out)
{
    __shared__ __align__(16) unsigned char Xhi[16 * PITCHB];   // 8448 B
    __shared__ __align__(16) unsigned char Xlo[16 * PITCHB];

    int item = blockIdx.x;
    bool is64 = (lim[1] == 0);
    int L = get_limit(lim, is64, item + 1) - get_limit(lim, is64, item);
    int s = 0, l = L;
    #pragma unroll
    for (int t = 0; t < 4; t++) { int pr = l >> 1; s += 2 * pr; l = (l + 1) >> 1; }
    int rowb = item * RPI;

    uint32_t XhiA = smem_u32(Xhi);
    uint32_t XloA = smem_u32(Xlo);
    int tid = threadIdx.x;
    int warp = tid >> 5, lane = tid & 31;
    int lrow = lane & 15;
    int lcol = (lane >> 4) << 3;
    uint32_t rowA = (uint32_t)lrow * PITCHB;

    #pragma unroll 1
    for (int lev = 0; lev < 4 && l >= 2; lev++) {
        int pairs = l >> 1;    // 1..8

        {
            const uint4* sh = (const uint4*)g_bufh;
            const uint4* sl = (const uint4*)g_bufl;
            int tot = pairs * 32;
            for (int f = tid; f < tot; f += 256) {
                int r = f >> 5, q = f & 31;
                long gsrc = (long)(rowb + s + 2 * r) * 16 + q;
                *(uint4*)(Xhi + r * PITCHB + q * 16) = sh[gsrc];
                *(uint4*)(Xlo + r * PITCHB + q * 16) = sl[gsrc];
            }
        }
        __syncthreads();

        // GEMM1: warp tile 16 x 32, fused terms
        float acc[4][4];
        #pragma unroll
        for (int nt = 0; nt < 4; nt++)
            #pragma unroll
            for (int e = 0; e < 4; e++) acc[nt][e] = 0.f;
        #pragma unroll 2
        for (int ks = 0; ks < 16; ks++) {
            uint32_t col2 = (uint32_t)(ks * 16 + lcol) * 2;
            uint32_t ah[4], al[4];
            ldm4(ah, XhiA + rowA + col2);
            ldm4(al, XloA + rowA + col2);
            #pragma unroll
            for (int nt = 0; nt < 4; nt++) {
                int bi = (ks * 32 + warp * 4 + nt) * 32 + lane;
                uint2 bh = g_W1hi[bi];
                uint2 bl = g_W1lo[bi];
                mma16816(acc[nt], ah, bh);
                mma16816(acc[nt], ah, bl);
                mma16816(acc[nt], al, bh);
            }
        }
        __syncthreads();

        {
            int row = lane >> 2;
            #pragma unroll
            for (int nt = 0; nt < 4; nt++) {
                int col = (warp * 4 + nt) * 8 + (lane & 3) * 2;
                float v0 = fmaxf(acc[nt][0] + b1[col], 0.f);
                float v1 = fmaxf(acc[nt][1] + b1[col + 1], 0.f);
                float v2 = fmaxf(acc[nt][2] + b1[col], 0.f);
                float v3 = fmaxf(acc[nt][3] + b1[col + 1], 0.f);
                unsigned short h0, l0_, h1, l1_, h2, l2_, h3, l3_;
                split2(v0, h0, l0_); split2(v1, h1, l1_);
                split2(v2, h2, l2_); split2(v3, h3, l3_);
                *(uint32_t*)(Xhi + row * PITCHB + col * 2)       = pk(h0, h1);
                *(uint32_t*)(Xlo + row * PITCHB + col * 2)       = pk(l0_, l1_);
                *(uint32_t*)(Xhi + (row + 8) * PITCHB + col * 2) = pk(h2, h3);
                *(uint32_t*)(Xlo + (row + 8) * PITCHB + col * 2) = pk(l2_, l3_);
            }
        }
        __syncthreads();

        // GEMM2: warp tile 16 x 16, fused terms
        float acc2[2][4];
        #pragma unroll
        for (int nt = 0; nt < 2; nt++)
            #pragma unroll
            for (int e = 0; e < 4; e++) acc2[nt][e] = 0.f;
        #pragma unroll 2
        for (int ks = 0; ks < 16; ks++) {
            uint32_t col2 = (uint32_t)(ks * 16 + lcol) * 2;
            uint32_t ah[4], al[4];
            ldm4(ah, XhiA + rowA + col2);
            ldm4(al, XloA + rowA + col2);
            #pragma unroll
            for (int nt = 0; nt < 2; nt++) {
                int bi = (ks * 16 + warp * 2 + nt) * 32 + lane;
                uint2 bh = g_W2hi[bi];
                uint2 bl = g_W2lo[bi];
                mma16816(acc2[nt], ah, bh);
                mma16816(acc2[nt], ah, bl);
                mma16816(acc2[nt], al, bh);
            }
        }
        __syncthreads();

        float* Ys = (float*)Xhi;
        {
            int row = lane >> 2;
            #pragma unroll
            for (int nt = 0; nt < 2; nt++) {
                int col = (warp * 2 + nt) * 8 + (lane & 3) * 2;
                *(float2*)(Ys + row * 132 + col) =
                    make_float2(acc2[nt][0] + b2[col], acc2[nt][1] + b2[col + 1]);
                *(float2*)(Ys + (row + 8) * 132 + col) =
                    make_float2(acc2[nt][2] + b2[col], acc2[nt][3] + b2[col + 1]);
            }
        }
        __syncthreads();

        if (warp < pairs) {
            int row = warp;
            long d = rowb + s + l + row;
            float4 y = *(const float4*)(Ys + row * 132 + lane * 4);
            float sum = y.x + y.y + y.z + y.w;
            float sq  = y.x * y.x + y.y * y.y + y.z * y.z + y.w * y.w;
            #pragma unroll
            for (int o = 16; o > 0; o >>= 1) {
                sum += __shfl_xor_sync(0xFFFFFFFFu, sum, o);
                sq  += __shfl_xor_sync(0xFFFFFFFFu, sq, o);
            }
            float mu  = sum * (1.f / 128.f);
            float var = sq * (1.f / 128.f) - mu * mu;
            float rs  = rsqrtf(var + 1e-5f);
            float4 wv = ((const float4*)lnw)[lane];
            float4 bv = ((const float4*)lnb)[lane];
            float4 o;
            o.x = (y.x - mu) * rs * wv.x + bv.x;
            o.y = (y.y - mu) * rs * wv.y + bv.y;
            o.z = (y.z - mu) * rs * wv.z + bv.z;
            o.w = (y.w - mu) * rs * wv.w + bv.w;
            unsigned short h0, l0_, h1, l1_, h2, l2_, h3, l3_;
            split2(o.x, h0, l0_); split2(o.y, h1, l1_);
            split2(o.z, h2, l2_); split2(o.w, h3, l3_);
            ((uint2*)g_bufh)[d * 32 + lane] = make_uint2(pk(h0, h1), pk(h2, h3));
            ((uint2*)g_bufl)[d * 32 + lane] = make_uint2(pk(l0_, l1_), pk(l2_, l3_));
        }
        s += 2 * pairs;
        l = (l + 1) >> 1;
        __syncthreads();
    }

    // ---- Gather fused: out[item] = hi + lo of root row (2L-2) ----
    if (tid < DIM) {
        long idx = ((long)rowb + (2 * L - 2)) * DIM + tid;
        out[item * DIM + tid] =
            __bfloat162float(g_bufh[idx]) + __bfloat162float(g_bufl[idx]);
    }
}

// ---------------------------------------------------------------------------
extern "C" void kernel_launch(void* const* d_in, const int* in_sizes, int n_in,
                              void* d_out, int out_size) {
    const float* args = (const float*)d_in[0];
    const int*   lim  = (const int*)d_in[1];
    const float* W1   = (const float*)d_in[2];
    const float* b1   = (const float*)d_in[3];
    const float* W2   = (const float*)d_in[4];
    const float* b2   = (const float*)d_in[5];
    const float* lnw  = (const float*)d_in[6];
    const float* lnb  = (const float*)d_in[7];
    float* out = (float*)d_out;
    (void)n_in; (void)out_size;

    int T = in_sizes[0] / DIM;   // total rows -> tight pair-count bounds

    cudaFuncSetAttribute(k_level_mma, cudaFuncAttributeMaxDynamicSharedMemorySize, 2 * XBYTES);

    dim3 gsc(4, NITEMS);
    k_scatter<<<gsc, 256>>>(args, lim);
    k_scan<<<1, NITEMS>>>(lim);
    k_fillw<<<NITEMS, 256>>>(lim, W1, W2);

    for (int k = 0; k < 4; k++) {
        // pairs_k <= T/2^(k+1) + NITEMS (odd-carry slack); CTAs early-exit on cnt
        int mp = (T >> (k + 1)) + NITEMS;
        int cap = NITEMS * (MAXM >> (k + 1));
        if (mp > cap) mp = cap;
        int ctas = (mp + TM - 1) / TM;
        k_level_mma<<<ctas, 256, 2 * XBYTES>>>(b1, b2, lnw, lnb, k);
    }
    k_finish<<<NITEMS, 256>>>(b1, b2, lnw, lnb, lim, out);
}